// round 9
// baseline (speedup 1.0000x reference)
#include <cuda_runtime.h>
#include <cuda_bf16.h>
#include <cstdint>
#include <math.h>

// Problem constants
#define BATCH   2
#define SEQ     2048
#define EMB     2048
#define NHEADS  32
#define NGROUPS 8
#define HDIM    64
#define KVDIM   (NGROUPS * HDIM)   // 512
#define ROWS    (BATCH * SEQ)      // 4096

// ---------------------------------------------------------------------------
// Scratch (no cudaMalloc allowed): Q [B,S,E], K/V [B,S,KVDIM], attn [B,S,E]
// ---------------------------------------------------------------------------
__device__ float g_Q[(size_t)ROWS * EMB];
__device__ float g_K[(size_t)ROWS * KVDIM];
__device__ float g_V[(size_t)ROWS * KVDIM];
__device__ float g_A[(size_t)ROWS * EMB];

// ---------------------------------------------------------------------------
// GEMM: C[M,N] = A[M,K] @ B[K,N] (+ bias per column), all row-major fp32.
// 128x128 block tile, BK=16, 256 threads, 8x8 micro-tile in 4+4 split layout.
// M % 128 == 0, N % 128 == 0, K % 16 == 0 (holds for all our shapes).
// ---------------------------------------------------------------------------
template <int WITH_BIAS>
__global__ __launch_bounds__(256, 2)
void gemm128_kernel(const float* __restrict__ A, const float* __restrict__ B,
                    float* __restrict__ C, int M, int N, int K,
                    const float* __restrict__ bias)
{
    __shared__ float As[16][132];   // transposed: As[k][m], padded stride
    __shared__ float Bs[16][132];   // Bs[k][n]

    const int tid = threadIdx.x;
    const int tr  = tid >> 4;       // 0..15
    const int tc  = tid & 15;       // 0..15
    const int m0  = blockIdx.y * 128;
    const int n0  = blockIdx.x * 128;

    float acc[8][8];
#pragma unroll
    for (int i = 0; i < 8; ++i)
#pragma unroll
        for (int j = 0; j < 8; ++j) acc[i][j] = 0.0f;

    const float* Abase = A + (size_t)m0 * K;
    const float* Bbase = B + n0;

    for (int k0 = 0; k0 < K; k0 += 16) {
        // Load A tile 128x16 (2 float4 per thread), store transposed
#pragma unroll
        for (int t = 0; t < 2; ++t) {
            int idx = tid + t * 256;
            int row = idx >> 2;          // 0..127
            int q   = idx & 3;           // which float4 within the 16-wide row
            float4 a = *(const float4*)(Abase + (size_t)row * K + k0 + q * 4);
            As[q * 4 + 0][row] = a.x;
            As[q * 4 + 1][row] = a.y;
            As[q * 4 + 2][row] = a.z;
            As[q * 4 + 3][row] = a.w;
        }
        // Load B tile 16x128 (2 float4 per thread)
#pragma unroll
        for (int t = 0; t < 2; ++t) {
            int idx = tid + t * 256;
            int kr  = idx >> 5;          // 0..15
            int c4  = (idx & 31) * 4;    // 0..124
            float4 b = *(const float4*)(Bbase + (size_t)(k0 + kr) * N + c4);
            *(float4*)&Bs[kr][c4] = b;
        }
        __syncthreads();

#pragma unroll
        for (int k = 0; k < 16; ++k) {
            float4 a0 = *(const float4*)&As[k][tr * 4];
            float4 a1 = *(const float4*)&As[k][64 + tr * 4];
            float4 b0 = *(const float4*)&Bs[k][tc * 4];
            float4 b1 = *(const float4*)&Bs[k][64 + tc * 4];
            float am[8] = {a0.x, a0.y, a0.z, a0.w, a1.x, a1.y, a1.z, a1.w};
            float bn[8] = {b0.x, b0.y, b0.z, b0.w, b1.x, b1.y, b1.z, b1.w};
#pragma unroll
            for (int i = 0; i < 8; ++i)
#pragma unroll
                for (int j = 0; j < 8; ++j)
                    acc[i][j] = fmaf(am[i], bn[j], acc[i][j]);
        }
        __syncthreads();
    }

    // Epilogue
#pragma unroll
    for (int ih = 0; ih < 2; ++ih) {
#pragma unroll
        for (int i = 0; i < 4; ++i) {
            int r = m0 + ih * 64 + tr * 4 + i;
            float* crow = C + (size_t)r * N + n0;
#pragma unroll
            for (int jh = 0; jh < 2; ++jh) {
                float4 v;
                v.x = acc[ih * 4 + i][jh * 4 + 0];
                v.y = acc[ih * 4 + i][jh * 4 + 1];
                v.z = acc[ih * 4 + i][jh * 4 + 2];
                v.w = acc[ih * 4 + i][jh * 4 + 3];
                if (WITH_BIAS) {
                    float4 bv = *(const float4*)(bias + n0 + jh * 64 + tc * 4);
                    v.x += bv.x; v.y += bv.y; v.z += bv.z; v.w += bv.w;
                }
                *(float4*)(crow + jh * 64 + tc * 4) = v;
            }
        }
    }
}

// ---------------------------------------------------------------------------
// Flash attention (causal, GQA rep=4). One block = one (b, h, 64-row q tile).
// 256 threads = 8 warps; warp w owns q rows 8w..8w+7; lane owns score/output
// columns {lane, lane+32}. Softmax state (m, l) is warp-local via shuffles.
// K and V share one smem buffer (loaded sequentially per k-tile).
// ---------------------------------------------------------------------------
#define KVSTRIDE 65   // pad so column-indexed (lane-varying row) access is conflict-free

__global__ __launch_bounds__(256, 2)
void flash_kernel(const float* __restrict__ Q, const float* __restrict__ Kb,
                  const float* __restrict__ Vb, float* __restrict__ Ab)
{
    const int qt = blockIdx.x;           // 0..31
    const int h  = blockIdx.y;           // 0..31
    const int b  = blockIdx.z;           // 0..1
    const int g  = h >> 2;               // kv group (rep = 4)

    const int tid  = threadIdx.x;
    const int warp = tid >> 5;
    const int lane = tid & 31;
    const int row0 = warp * 8;           // this warp's q rows within tile

    __shared__ float Qs[64][64];
    __shared__ float KVs[64][KVSTRIDE];

    const int q0 = qt * 64;

    // Load Q tile: Q[b, q0+r, h*64 + c]
    {
        const float* qbase = Q + ((size_t)b * SEQ + q0) * EMB + h * HDIM;
#pragma unroll
        for (int p = 0; p < 4; ++p) {
            int r = p * 16 + (tid >> 4);
            int c = (tid & 15) * 4;
            float4 v = *(const float4*)(qbase + (size_t)r * EMB + c);
            *(float4*)&Qs[r][c] = v;
        }
    }

    float m[8], l[8], acc0[8], acc1[8];
#pragma unroll
    for (int rr = 0; rr < 8; ++rr) {
        m[rr] = -INFINITY; l[rr] = 0.0f; acc0[rr] = 0.0f; acc1[rr] = 0.0f;
    }

    const float scale = 0.125f;  // 64^-0.5
    const float* kbase = Kb + (size_t)b * SEQ * KVDIM + g * HDIM;
    const float* vbase = Vb + (size_t)b * SEQ * KVDIM + g * HDIM;

    const int nkt = qt + 1;  // causal: only k tiles <= q tile
    for (int kt = 0; kt < nkt; ++kt) {
        const int k0 = kt * 64;

        __syncthreads();  // prior PV reads done before overwriting KVs
        // Load K tile: KVs[j][d] = K[b, k0+j, g*64+d]
#pragma unroll
        for (int p = 0; p < 4; ++p) {
            int j = p * 16 + (tid >> 4);
            int c = (tid & 15) * 4;
            float4 v = *(const float4*)(kbase + (size_t)(k0 + j) * KVDIM + c);
            KVs[j][c + 0] = v.x; KVs[j][c + 1] = v.y;
            KVs[j][c + 2] = v.z; KVs[j][c + 3] = v.w;
        }
        __syncthreads();

        // Scores: s[rr][0] = q_row . k_lane, s[rr][1] = q_row . k_{lane+32}
        float s0[8], s1[8];
#pragma unroll
        for (int rr = 0; rr < 8; ++rr) { s0[rr] = 0.0f; s1[rr] = 0.0f; }
#pragma unroll 4
        for (int d = 0; d < 64; d += 2) {
            float ka0 = KVs[lane][d],      ka1 = KVs[lane][d + 1];
            float kb0 = KVs[lane + 32][d], kb1 = KVs[lane + 32][d + 1];
#pragma unroll
            for (int rr = 0; rr < 8; ++rr) {
                float2 qv = *(const float2*)&Qs[row0 + rr][d];
                s0[rr] = fmaf(qv.x, ka0, s0[rr]);
                s0[rr] = fmaf(qv.y, ka1, s0[rr]);
                s1[rr] = fmaf(qv.x, kb0, s1[rr]);
                s1[rr] = fmaf(qv.y, kb1, s1[rr]);
            }
        }

        // Causal mask (only the diagonal tile has masked entries)
        if (kt == qt) {
#pragma unroll
            for (int rr = 0; rr < 8; ++rr) {
                int qi = row0 + rr;  // local index == local k index scale
                if (lane > qi)      s0[rr] = -INFINITY;
                if (lane + 32 > qi) s1[rr] = -INFINITY;
            }
        }

        // Online softmax (warp-local per row)
#pragma unroll
        for (int rr = 0; rr < 8; ++rr) {
            float a = s0[rr] * scale;
            float c = s1[rr] * scale;
            float mx = fmaxf(a, c);
#pragma unroll
            for (int off = 16; off; off >>= 1)
                mx = fmaxf(mx, __shfl_xor_sync(0xffffffffu, mx, off));
            float mnew  = fmaxf(m[rr], mx);
            float alpha = __expf(m[rr] - mnew);
            float p0 = __expf(a - mnew);
            float p1 = __expf(c - mnew);
            float sum = p0 + p1;
#pragma unroll
            for (int off = 16; off; off >>= 1)
                sum += __shfl_xor_sync(0xffffffffu, sum, off);
            l[rr] = l[rr] * alpha + sum;
            m[rr] = mnew;
            acc0[rr] *= alpha;
            acc1[rr] *= alpha;
            s0[rr] = p0;
            s1[rr] = p1;
        }

        __syncthreads();  // scores finished reading K before V overwrite
        // Load V tile into the same buffer
#pragma unroll
        for (int p = 0; p < 4; ++p) {
            int j = p * 16 + (tid >> 4);
            int c = (tid & 15) * 4;
            float4 v = *(const float4*)(vbase + (size_t)(k0 + j) * KVDIM + c);
            KVs[j][c + 0] = v.x; KVs[j][c + 1] = v.y;
            KVs[j][c + 2] = v.z; KVs[j][c + 3] = v.w;
        }
        __syncthreads();

        // P @ V: acc[rr][dc] += sum_j p[rr][j] * V[j][dc]
        // p[rr][j] lives in lane (j & 31)'s registers -> shuffle broadcast.
#pragma unroll
        for (int half = 0; half < 2; ++half) {
#pragma unroll 4
            for (int jl = 0; jl < 32; ++jl) {
                int j = half * 32 + jl;
                float v0 = KVs[j][lane];
                float v1 = KVs[j][lane + 32];
#pragma unroll
                for (int rr = 0; rr < 8; ++rr) {
                    float pj = __shfl_sync(0xffffffffu,
                                           (half == 0) ? s0[rr] : s1[rr], jl);
                    acc0[rr] = fmaf(pj, v0, acc0[rr]);
                    acc1[rr] = fmaf(pj, v1, acc1[rr]);
                }
            }
        }
    }

    // Finalize and write attn[b, qi, h*64 + d]
#pragma unroll
    for (int rr = 0; rr < 8; ++rr) {
        float inv = 1.0f / l[rr];
        int qi = q0 + row0 + rr;
        float* out = Ab + ((size_t)b * SEQ + qi) * EMB + h * HDIM;
        out[lane]      = acc0[rr] * inv;
        out[lane + 32] = acc1[rr] * inv;
    }
}

// ---------------------------------------------------------------------------
// Launch: 3 projection GEMMs -> flash attention -> output GEMM (+bias).
// All on the default stream (graph-capturable, no allocs, no syncs).
// ---------------------------------------------------------------------------
extern "C" void kernel_launch(void* const* d_in, const int* in_sizes, int n_in,
                              void* d_out, int out_size)
{
    const float* x  = (const float*)d_in[0];
    const float* Wq = (const float*)d_in[1];
    const float* Wk = (const float*)d_in[2];
    const float* Wv = (const float*)d_in[3];
    const float* Wo = (const float*)d_in[4];
    const float* bo = (const float*)d_in[5];
    // d_in[6] is the causal mask; applied analytically in flash_kernel.
    float* out = (float*)d_out;

    float *Qp, *Kp, *Vp, *Ap;
    cudaGetSymbolAddress((void**)&Qp, g_Q);
    cudaGetSymbolAddress((void**)&Kp, g_K);
    cudaGetSymbolAddress((void**)&Vp, g_V);
    cudaGetSymbolAddress((void**)&Ap, g_A);

    dim3 blk(256);
    // Q = x @ Wq   [4096,2048] = [4096,2048]@[2048,2048]
    gemm128_kernel<0><<<dim3(EMB / 128, ROWS / 128), blk>>>(x, Wq, Qp, ROWS, EMB, EMB, nullptr);
    // K = x @ Wk, V = x @ Wv   [4096,512]
    gemm128_kernel<0><<<dim3(KVDIM / 128, ROWS / 128), blk>>>(x, Wk, Kp, ROWS, KVDIM, EMB, nullptr);
    gemm128_kernel<0><<<dim3(KVDIM / 128, ROWS / 128), blk>>>(x, Wv, Vp, ROWS, KVDIM, EMB, nullptr);
    // Flash attention -> g_A (already in [B,S,H*D] layout)
    flash_kernel<<<dim3(SEQ / 64, NHEADS, BATCH), blk>>>(Qp, Kp, Vp, Ap);
    // out = attn @ Wo + bo
    gemm128_kernel<1><<<dim3(EMB / 128, ROWS / 128), blk>>>(Ap, Wo, out, ROWS, EMB, EMB, bo);
}

// round 12
// speedup vs baseline: 1.2783x; 1.2783x over previous
#include <cuda_runtime.h>
#include <cuda_bf16.h>
#include <cstdint>
#include <math.h>

// Problem constants
#define BATCH   2
#define SEQ     2048
#define EMB     2048
#define NHEADS  32
#define NGROUPS 8
#define HDIM    64
#define KVDIM   (NGROUPS * HDIM)   // 512
#define ROWS    (BATCH * SEQ)      // 4096
#define GK      2048               // reduction dim for all GEMMs

// ---------------------------------------------------------------------------
// Scratch (no cudaMalloc allowed)
// ---------------------------------------------------------------------------
__device__ float g_Q[(size_t)ROWS * EMB];
__device__ float g_K[(size_t)ROWS * KVDIM];
__device__ float g_V[(size_t)ROWS * KVDIM];
__device__ float g_A[(size_t)ROWS * EMB];

// bf16 hi/lo split operands (16B aligned for uint4 loads)
__device__ __align__(16) __nv_bfloat16 g_xh[(size_t)ROWS * EMB];
__device__ __align__(16) __nv_bfloat16 g_xl[(size_t)ROWS * EMB];
__device__ __align__(16) __nv_bfloat16 g_ah[(size_t)ROWS * EMB];
__device__ __align__(16) __nv_bfloat16 g_al[(size_t)ROWS * EMB];
// Transposed weights [N, K] bf16 hi/lo
__device__ __align__(16) __nv_bfloat16 g_Wqh[(size_t)EMB * EMB],   g_Wql[(size_t)EMB * EMB];
__device__ __align__(16) __nv_bfloat16 g_Wkh[(size_t)KVDIM * EMB], g_Wkl[(size_t)KVDIM * EMB];
__device__ __align__(16) __nv_bfloat16 g_Wvh[(size_t)KVDIM * EMB], g_Wvl[(size_t)KVDIM * EMB];
__device__ __align__(16) __nv_bfloat16 g_Woh[(size_t)EMB * EMB],   g_Wol[(size_t)EMB * EMB];

// ---------------------------------------------------------------------------
// Warp-MMA primitives (arch-neutral: valid on plain sm_103 target)
// ---------------------------------------------------------------------------
__device__ __forceinline__ uint32_t smem_u32(const void* p) {
    uint32_t a;
    asm("{ .reg .u64 t; cvta.to.shared.u64 t, %1; cvt.u32.u64 %0, t; }"
        : "=r"(a) : "l"(p));
    return a;
}

__device__ __forceinline__ void ldmx4(uint32_t addr, uint32_t& r0, uint32_t& r1,
                                      uint32_t& r2, uint32_t& r3) {
    asm volatile("ldmatrix.sync.aligned.m8n8.x4.shared.b16 {%0,%1,%2,%3}, [%4];"
                 : "=r"(r0), "=r"(r1), "=r"(r2), "=r"(r3) : "r"(addr));
}

__device__ __forceinline__ void mma16816(float* c, const uint32_t* a,
                                         uint32_t b0, uint32_t b1) {
    asm volatile(
        "mma.sync.aligned.m16n8k16.row.col.f32.bf16.bf16.f32 "
        "{%0,%1,%2,%3}, {%4,%5,%6,%7}, {%8,%9}, {%0,%1,%2,%3};"
        : "+f"(c[0]), "+f"(c[1]), "+f"(c[2]), "+f"(c[3])
        : "r"(a[0]), "r"(a[1]), "r"(a[2]), "r"(a[3]), "r"(b0), "r"(b1));
}

// ---------------------------------------------------------------------------
// Conversion: fp32 [R,K] -> bf16 hi/lo [R,K]
// ---------------------------------------------------------------------------
__global__ void convert_hilo(const float* __restrict__ in,
                             __nv_bfloat16* __restrict__ oh,
                             __nv_bfloat16* __restrict__ ol, int n4)
{
    int idx = blockIdx.x * blockDim.x + threadIdx.x;
    if (idx >= n4) return;
    float4 v = ((const float4*)in)[idx];
    __nv_bfloat16 h[4], l[4];
    float f[4] = {v.x, v.y, v.z, v.w};
#pragma unroll
    for (int i = 0; i < 4; ++i) {
        h[i] = __float2bfloat16(f[i]);
        l[i] = __float2bfloat16(f[i] - __bfloat162float(h[i]));
    }
    ((uint2*)oh)[idx] = *(uint2*)h;
    ((uint2*)ol)[idx] = *(uint2*)l;
}

// ---------------------------------------------------------------------------
// Transpose + convert: fp32 [K,N] -> bf16 hi/lo [N,K]
// ---------------------------------------------------------------------------
__global__ void transpose_hilo(const float* __restrict__ in,
                               __nv_bfloat16* __restrict__ oh,
                               __nv_bfloat16* __restrict__ ol, int K, int N)
{
    __shared__ float t[32][33];
    int n0 = blockIdx.x * 32;
    int k0 = blockIdx.y * 32;
    int tx = threadIdx.x, ty = threadIdx.y;
#pragma unroll
    for (int i = 0; i < 4; ++i) {
        int k = k0 + ty + i * 8;
        t[ty + i * 8][tx] = in[(size_t)k * N + n0 + tx];
    }
    __syncthreads();
#pragma unroll
    for (int i = 0; i < 4; ++i) {
        int n = n0 + ty + i * 8;
        float v = t[tx][ty + i * 8];
        __nv_bfloat16 h = __float2bfloat16(v);
        __nv_bfloat16 l = __float2bfloat16(v - __bfloat162float(h));
        oh[(size_t)n * K + k0 + tx] = h;
        ol[(size_t)n * K + k0 + tx] = l;
    }
}

// ---------------------------------------------------------------------------
// HMMA GEMM, 3-term hi/lo split, fp32 accumulate.
// C[M,N] = Ah@Bh^T + Al@Bh^T + Ah@Bl^T ; A:[M,2048], B:[N,2048] both K-major.
// CTA tile 128x256, BK=32, 8 warps (2x4), warp tile 64x64, double-buffered.
// ASTRIDE=40 bf16 (80 B): 16B-aligned rows AND conflict-free ldmatrix phases.
// ---------------------------------------------------------------------------
#define BM 128
#define BN 256
#define BKK 32
#define ASTRIDE 40                    // bf16 units per smem row (80 B, 16B-mult)
#define ABUF (BM * ASTRIDE)           // 5120 units
#define BBUF (BN * ASTRIDE)           // 10240 units
#define BUFU (ABUF + BBUF)            // 15360 units per stage
#define KSTEPS (GK / BKK)             // 64
#define NT (3 * KSTEPS)               // 192

__global__ __launch_bounds__(256)
void gemm_hmma(const __nv_bfloat16* __restrict__ Ah, const __nv_bfloat16* __restrict__ Al,
               const __nv_bfloat16* __restrict__ Bh, const __nv_bfloat16* __restrict__ Bl,
               float* __restrict__ C, int N, const float* __restrict__ bias)
{
    extern __shared__ __nv_bfloat16 sm[];

    const int tid  = threadIdx.x;
    const int wid  = tid >> 5;
    const int lane = tid & 31;
    const int m0   = blockIdx.y * BM;
    const int n0   = blockIdx.x * BN;
    const int wm0  = (wid & 1) * 64;      // warp m offset in CTA tile
    const int wn0  = (wid >> 1) * 64;     // warp n offset

    const __nv_bfloat16* Aop[3] = {Ah, Al, Ah};
    const __nv_bfloat16* Bop[3] = {Bh, Bh, Bl};

    const uint32_t sbase = smem_u32(sm);

    float acc[4][8][4];
#pragma unroll
    for (int i = 0; i < 4; ++i)
#pragma unroll
        for (int j = 0; j < 8; ++j)
#pragma unroll
            for (int k = 0; k < 4; ++k) acc[i][j][k] = 0.0f;

    // global->smem tiling: 16B chunks, 4 per 32-elem row
    const int ar = tid >> 2;          // 0..63
    const int ac = tid & 3;           // chunk in row

    uint4 pa[2], pb[4];
    auto prefetch = [&](int p, int k0) {
        const __nv_bfloat16* A = Aop[p];
        const __nv_bfloat16* B = Bop[p];
        pa[0] = *(const uint4*)(A + (size_t)(m0 + ar) * GK + k0 + ac * 8);
        pa[1] = *(const uint4*)(A + (size_t)(m0 + ar + 64) * GK + k0 + ac * 8);
#pragma unroll
        for (int i = 0; i < 4; ++i)
            pb[i] = *(const uint4*)(B + (size_t)(n0 + ar + i * 64) * GK + k0 + ac * 8);
    };
    auto commit = [&](int buf) {
        __nv_bfloat16* s = sm + buf * BUFU;
        *(uint4*)(s + ar * ASTRIDE + ac * 8)        = pa[0];
        *(uint4*)(s + (ar + 64) * ASTRIDE + ac * 8) = pa[1];
        __nv_bfloat16* sb = s + ABUF;
#pragma unroll
        for (int i = 0; i < 4; ++i)
            *(uint4*)(sb + (ar + i * 64) * ASTRIDE + ac * 8) = pb[i];
    };

    // ldmatrix per-lane offsets
    const int aRow = lane & 15;
    const int aK   = ((lane >> 4) & 1) * 8;
    const int bRow = (lane & 7) | ((lane & 16) >> 1);
    const int bK   = lane & 8;

    prefetch(0, 0);
    commit(0);
    __syncthreads();

    for (int t = 0; t < NT; ++t) {
        const int cur = t & 1;
        if (t + 1 < NT) {
            const int tn = t + 1;
            prefetch(tn >> 6, (tn & (KSTEPS - 1)) * BKK);
        }
        const uint32_t sA = sbase + cur * (BUFU * 2);
        const uint32_t sB = sA + ABUF * 2;

#pragma unroll
        for (int kk = 0; kk < 2; ++kk) {
            uint32_t a[4][4];
#pragma unroll
            for (int mt = 0; mt < 4; ++mt)
                ldmx4(sA + (uint32_t)(((wm0 + mt * 16 + aRow) * ASTRIDE + kk * 16 + aK) * 2),
                      a[mt][0], a[mt][1], a[mt][2], a[mt][3]);
#pragma unroll
            for (int nt = 0; nt < 4; ++nt) {
                uint32_t b0, b1, b2, b3;
                ldmx4(sB + (uint32_t)(((wn0 + nt * 16 + bRow) * ASTRIDE + kk * 16 + bK) * 2),
                      b0, b1, b2, b3);
#pragma unroll
                for (int mt = 0; mt < 4; ++mt) {
                    mma16816(acc[mt][2 * nt + 0], a[mt], b0, b1);
                    mma16816(acc[mt][2 * nt + 1], a[mt], b2, b3);
                }
            }
        }
        if (t + 1 < NT) commit((t + 1) & 1);
        __syncthreads();
    }

    // Epilogue: direct fp32 stores (float2 per fragment row)
    const int g  = lane >> 2;
    const int tq = lane & 3;
#pragma unroll
    for (int mt = 0; mt < 4; ++mt) {
#pragma unroll
        for (int n8 = 0; n8 < 8; ++n8) {
            int r  = m0 + wm0 + mt * 16 + g;
            int cc = n0 + wn0 + n8 * 8 + tq * 2;
            float2 v0 = make_float2(acc[mt][n8][0], acc[mt][n8][1]);
            float2 v1 = make_float2(acc[mt][n8][2], acc[mt][n8][3]);
            if (bias) {
                float2 bv = *(const float2*)(bias + cc);
                v0.x += bv.x; v0.y += bv.y;
                v1.x += bv.x; v1.y += bv.y;
            }
            *(float2*)(C + (size_t)r * N + cc)       = v0;
            *(float2*)(C + (size_t)(r + 8) * N + cc) = v1;
        }
    }
}

// ---------------------------------------------------------------------------
// Flash attention (causal, GQA rep=4) — unchanged from the passing R9 kernel.
// ---------------------------------------------------------------------------
#define KVSTRIDE 65

__global__ __launch_bounds__(256, 2)
void flash_kernel(const float* __restrict__ Q, const float* __restrict__ Kb,
                  const float* __restrict__ Vb, float* __restrict__ Ab)
{
    const int qt = blockIdx.x;
    const int h  = blockIdx.y;
    const int b  = blockIdx.z;
    const int g  = h >> 2;

    const int tid  = threadIdx.x;
    const int warp = tid >> 5;
    const int lane = tid & 31;
    const int row0 = warp * 8;

    __shared__ float Qs[64][64];
    __shared__ float KVs[64][KVSTRIDE];

    const int q0 = qt * 64;

    {
        const float* qbase = Q + ((size_t)b * SEQ + q0) * EMB + h * HDIM;
#pragma unroll
        for (int p = 0; p < 4; ++p) {
            int r = p * 16 + (tid >> 4);
            int c = (tid & 15) * 4;
            float4 v = *(const float4*)(qbase + (size_t)r * EMB + c);
            *(float4*)&Qs[r][c] = v;
        }
    }

    float m[8], l[8], acc0[8], acc1[8];
#pragma unroll
    for (int rr = 0; rr < 8; ++rr) {
        m[rr] = -INFINITY; l[rr] = 0.0f; acc0[rr] = 0.0f; acc1[rr] = 0.0f;
    }

    const float scale = 0.125f;
    const float* kbase = Kb + (size_t)b * SEQ * KVDIM + g * HDIM;
    const float* vbase = Vb + (size_t)b * SEQ * KVDIM + g * HDIM;

    const int nkt = qt + 1;
    for (int kt = 0; kt < nkt; ++kt) {
        const int k0 = kt * 64;

        __syncthreads();
#pragma unroll
        for (int p = 0; p < 4; ++p) {
            int j = p * 16 + (tid >> 4);
            int c = (tid & 15) * 4;
            float4 v = *(const float4*)(kbase + (size_t)(k0 + j) * KVDIM + c);
            KVs[j][c + 0] = v.x; KVs[j][c + 1] = v.y;
            KVs[j][c + 2] = v.z; KVs[j][c + 3] = v.w;
        }
        __syncthreads();

        float s0[8], s1[8];
#pragma unroll
        for (int rr = 0; rr < 8; ++rr) { s0[rr] = 0.0f; s1[rr] = 0.0f; }
#pragma unroll 4
        for (int d = 0; d < 64; d += 2) {
            float ka0 = KVs[lane][d],      ka1 = KVs[lane][d + 1];
            float kb0 = KVs[lane + 32][d], kb1 = KVs[lane + 32][d + 1];
#pragma unroll
            for (int rr = 0; rr < 8; ++rr) {
                float2 qv = *(const float2*)&Qs[row0 + rr][d];
                s0[rr] = fmaf(qv.x, ka0, s0[rr]);
                s0[rr] = fmaf(qv.y, ka1, s0[rr]);
                s1[rr] = fmaf(qv.x, kb0, s1[rr]);
                s1[rr] = fmaf(qv.y, kb1, s1[rr]);
            }
        }

        if (kt == qt) {
#pragma unroll
            for (int rr = 0; rr < 8; ++rr) {
                int qi = row0 + rr;
                if (lane > qi)      s0[rr] = -INFINITY;
                if (lane + 32 > qi) s1[rr] = -INFINITY;
            }
        }

#pragma unroll
        for (int rr = 0; rr < 8; ++rr) {
            float a = s0[rr] * scale;
            float c = s1[rr] * scale;
            float mx = fmaxf(a, c);
#pragma unroll
            for (int off = 16; off; off >>= 1)
                mx = fmaxf(mx, __shfl_xor_sync(0xffffffffu, mx, off));
            float mnew  = fmaxf(m[rr], mx);
            float alpha = __expf(m[rr] - mnew);
            float p0 = __expf(a - mnew);
            float p1 = __expf(c - mnew);
            float sum = p0 + p1;
#pragma unroll
            for (int off = 16; off; off >>= 1)
                sum += __shfl_xor_sync(0xffffffffu, sum, off);
            l[rr] = l[rr] * alpha + sum;
            m[rr] = mnew;
            acc0[rr] *= alpha;
            acc1[rr] *= alpha;
            s0[rr] = p0;
            s1[rr] = p1;
        }

        __syncthreads();
#pragma unroll
        for (int p = 0; p < 4; ++p) {
            int j = p * 16 + (tid >> 4);
            int c = (tid & 15) * 4;
            float4 v = *(const float4*)(vbase + (size_t)(k0 + j) * KVDIM + c);
            KVs[j][c + 0] = v.x; KVs[j][c + 1] = v.y;
            KVs[j][c + 2] = v.z; KVs[j][c + 3] = v.w;
        }
        __syncthreads();

#pragma unroll
        for (int half = 0; half < 2; ++half) {
#pragma unroll 4
            for (int jl = 0; jl < 32; ++jl) {
                int j = half * 32 + jl;
                float v0 = KVs[j][lane];
                float v1 = KVs[j][lane + 32];
#pragma unroll
                for (int rr = 0; rr < 8; ++rr) {
                    float pj = __shfl_sync(0xffffffffu,
                                           (half == 0) ? s0[rr] : s1[rr], jl);
                    acc0[rr] = fmaf(pj, v0, acc0[rr]);
                    acc1[rr] = fmaf(pj, v1, acc1[rr]);
                }
            }
        }
    }

#pragma unroll
    for (int rr = 0; rr < 8; ++rr) {
        float inv = 1.0f / l[rr];
        int qi = q0 + row0 + rr;
        float* out = Ab + ((size_t)b * SEQ + qi) * EMB + h * HDIM;
        out[lane]      = acc0[rr] * inv;
        out[lane + 32] = acc1[rr] * inv;
    }
}

// ---------------------------------------------------------------------------
// Launch
// ---------------------------------------------------------------------------
extern "C" void kernel_launch(void* const* d_in, const int* in_sizes, int n_in,
                              void* d_out, int out_size)
{
    const float* x  = (const float*)d_in[0];
    const float* Wq = (const float*)d_in[1];
    const float* Wk = (const float*)d_in[2];
    const float* Wv = (const float*)d_in[3];
    const float* Wo = (const float*)d_in[4];
    const float* bo = (const float*)d_in[5];
    float* out = (float*)d_out;

    float *Qp, *Kp, *Vp, *Ap;
    cudaGetSymbolAddress((void**)&Qp, g_Q);
    cudaGetSymbolAddress((void**)&Kp, g_K);
    cudaGetSymbolAddress((void**)&Vp, g_V);
    cudaGetSymbolAddress((void**)&Ap, g_A);

    __nv_bfloat16 *xh, *xl, *ah, *al;
    __nv_bfloat16 *wqh, *wql, *wkh, *wkl, *wvh, *wvl, *woh, *wol;
    cudaGetSymbolAddress((void**)&xh, g_xh);   cudaGetSymbolAddress((void**)&xl, g_xl);
    cudaGetSymbolAddress((void**)&ah, g_ah);   cudaGetSymbolAddress((void**)&al, g_al);
    cudaGetSymbolAddress((void**)&wqh, g_Wqh); cudaGetSymbolAddress((void**)&wql, g_Wql);
    cudaGetSymbolAddress((void**)&wkh, g_Wkh); cudaGetSymbolAddress((void**)&wkl, g_Wkl);
    cudaGetSymbolAddress((void**)&wvh, g_Wvh); cudaGetSymbolAddress((void**)&wvl, g_Wvl);
    cudaGetSymbolAddress((void**)&woh, g_Woh); cudaGetSymbolAddress((void**)&wol, g_Wol);

    const int SMEM_DYN = 2 * (BUFU * 2);   // 61440 B: two 30720 B stages
    cudaFuncSetAttribute(gemm_hmma, cudaFuncAttributeMaxDynamicSharedMemorySize, SMEM_DYN);

    // 1. Convert x -> bf16 hi/lo
    {
        int n4 = ROWS * EMB / 4;
        convert_hilo<<<(n4 + 255) / 256, 256>>>(x, xh, xl, n4);
    }
    // 2. Transpose+convert weights -> [N,K] bf16 hi/lo
    transpose_hilo<<<dim3(EMB / 32,   EMB / 32), dim3(32, 8)>>>(Wq, wqh, wql, EMB, EMB);
    transpose_hilo<<<dim3(KVDIM / 32, EMB / 32), dim3(32, 8)>>>(Wk, wkh, wkl, EMB, KVDIM);
    transpose_hilo<<<dim3(KVDIM / 32, EMB / 32), dim3(32, 8)>>>(Wv, wvh, wvl, EMB, KVDIM);
    transpose_hilo<<<dim3(EMB / 32,   EMB / 32), dim3(32, 8)>>>(Wo, woh, wol, EMB, EMB);

    // 3. Projections on tensor cores (HMMA)
    gemm_hmma<<<dim3(EMB / BN,   ROWS / BM), 256, SMEM_DYN>>>(xh, xl, wqh, wql, Qp, EMB,   nullptr);
    gemm_hmma<<<dim3(KVDIM / BN, ROWS / BM), 256, SMEM_DYN>>>(xh, xl, wkh, wkl, Kp, KVDIM, nullptr);
    gemm_hmma<<<dim3(KVDIM / BN, ROWS / BM), 256, SMEM_DYN>>>(xh, xl, wvh, wvl, Vp, KVDIM, nullptr);

    // 4. Flash attention (fp32)
    flash_kernel<<<dim3(SEQ / 64, NHEADS, BATCH), 256>>>(Qp, Kp, Vp, Ap);

    // 5. attn -> bf16 hi/lo, output projection + bias
    {
        int n4 = ROWS * EMB / 4;
        convert_hilo<<<(n4 + 255) / 256, 256>>>(Ap, ah, al, n4);
    }
    gemm_hmma<<<dim3(EMB / BN, ROWS / BM), 256, SMEM_DYN>>>(ah, al, woh, wol, out, EMB, bo);
}

// round 13
// speedup vs baseline: 1.9765x; 1.5462x over previous
#include <cuda_runtime.h>
#include <cuda_bf16.h>
#include <cstdint>
#include <math.h>

// Problem constants
#define BATCH   2
#define SEQ     2048
#define EMB     2048
#define NHEADS  32
#define NGROUPS 8
#define HDIM    64
#define KVDIM   (NGROUPS * HDIM)   // 512
#define ROWS    (BATCH * SEQ)      // 4096
#define GK      2048               // reduction dim for projection GEMMs

// ---------------------------------------------------------------------------
// Scratch (no cudaMalloc allowed)
// ---------------------------------------------------------------------------
__device__ float g_Q[(size_t)ROWS * EMB];
__device__ float g_K[(size_t)ROWS * KVDIM];
__device__ float g_V[(size_t)ROWS * KVDIM];
__device__ float g_A[(size_t)ROWS * EMB];

// bf16 hi/lo split operands (16B aligned for uint4 loads)
__device__ __align__(16) __nv_bfloat16 g_xh[(size_t)ROWS * EMB];
__device__ __align__(16) __nv_bfloat16 g_xl[(size_t)ROWS * EMB];
__device__ __align__(16) __nv_bfloat16 g_ah[(size_t)ROWS * EMB];
__device__ __align__(16) __nv_bfloat16 g_al[(size_t)ROWS * EMB];
// Transposed weights [N, K] bf16 hi/lo
__device__ __align__(16) __nv_bfloat16 g_Wqh[(size_t)EMB * EMB],   g_Wql[(size_t)EMB * EMB];
__device__ __align__(16) __nv_bfloat16 g_Wkh[(size_t)KVDIM * EMB], g_Wkl[(size_t)KVDIM * EMB];
__device__ __align__(16) __nv_bfloat16 g_Wvh[(size_t)KVDIM * EMB], g_Wvl[(size_t)KVDIM * EMB];
__device__ __align__(16) __nv_bfloat16 g_Woh[(size_t)EMB * EMB],   g_Wol[(size_t)EMB * EMB];
// flash operands: Q (pre-scaled), K hi/lo; V transposed [B,G,D,S] hi/lo
__device__ __align__(16) __nv_bfloat16 g_qh[(size_t)ROWS * EMB];
__device__ __align__(16) __nv_bfloat16 g_ql[(size_t)ROWS * EMB];
__device__ __align__(16) __nv_bfloat16 g_kh[(size_t)ROWS * KVDIM];
__device__ __align__(16) __nv_bfloat16 g_kl[(size_t)ROWS * KVDIM];
__device__ __align__(16) __nv_bfloat16 g_vth[(size_t)ROWS * KVDIM];
__device__ __align__(16) __nv_bfloat16 g_vtl[(size_t)ROWS * KVDIM];

// ---------------------------------------------------------------------------
// Warp-MMA primitives (arch-neutral: valid on plain sm_103 target)
// ---------------------------------------------------------------------------
__device__ __forceinline__ uint32_t smem_u32(const void* p) {
    uint32_t a;
    asm("{ .reg .u64 t; cvta.to.shared.u64 t, %1; cvt.u32.u64 %0, t; }"
        : "=r"(a) : "l"(p));
    return a;
}

__device__ __forceinline__ void ldmx4(uint32_t addr, uint32_t& r0, uint32_t& r1,
                                      uint32_t& r2, uint32_t& r3) {
    asm volatile("ldmatrix.sync.aligned.m8n8.x4.shared.b16 {%0,%1,%2,%3}, [%4];"
                 : "=r"(r0), "=r"(r1), "=r"(r2), "=r"(r3) : "r"(addr));
}

__device__ __forceinline__ void mma16816(float* c, const uint32_t* a,
                                         uint32_t b0, uint32_t b1) {
    asm volatile(
        "mma.sync.aligned.m16n8k16.row.col.f32.bf16.bf16.f32 "
        "{%0,%1,%2,%3}, {%4,%5,%6,%7}, {%8,%9}, {%0,%1,%2,%3};"
        : "+f"(c[0]), "+f"(c[1]), "+f"(c[2]), "+f"(c[3])
        : "r"(a[0]), "r"(a[1]), "r"(a[2]), "r"(a[3]), "r"(b0), "r"(b1));
}

__device__ __forceinline__ uint32_t packbf(__nv_bfloat16 a, __nv_bfloat16 b) {
    __nv_bfloat162 t = __halves2bfloat162(a, b);
    return *reinterpret_cast<uint32_t*>(&t);
}

// ---------------------------------------------------------------------------
// Conversion: fp32 [R,K] -> bf16 hi/lo [R,K], optional scale
// ---------------------------------------------------------------------------
__global__ void convert_hilo(const float* __restrict__ in,
                             __nv_bfloat16* __restrict__ oh,
                             __nv_bfloat16* __restrict__ ol, int n4, float scale)
{
    int idx = blockIdx.x * blockDim.x + threadIdx.x;
    if (idx >= n4) return;
    float4 v = ((const float4*)in)[idx];
    __nv_bfloat16 h[4], l[4];
    float f[4] = {v.x * scale, v.y * scale, v.z * scale, v.w * scale};
#pragma unroll
    for (int i = 0; i < 4; ++i) {
        h[i] = __float2bfloat16(f[i]);
        l[i] = __float2bfloat16(f[i] - __bfloat162float(h[i]));
    }
    ((uint2*)oh)[idx] = *(uint2*)h;
    ((uint2*)ol)[idx] = *(uint2*)l;
}

// ---------------------------------------------------------------------------
// Transpose + convert: fp32 [K,N] -> bf16 hi/lo [N,K]   (weights)
// ---------------------------------------------------------------------------
__global__ void transpose_hilo(const float* __restrict__ in,
                               __nv_bfloat16* __restrict__ oh,
                               __nv_bfloat16* __restrict__ ol, int K, int N)
{
    __shared__ float t[32][33];
    int n0 = blockIdx.x * 32;
    int k0 = blockIdx.y * 32;
    int tx = threadIdx.x, ty = threadIdx.y;
#pragma unroll
    for (int i = 0; i < 4; ++i) {
        int k = k0 + ty + i * 8;
        t[ty + i * 8][tx] = in[(size_t)k * N + n0 + tx];
    }
    __syncthreads();
#pragma unroll
    for (int i = 0; i < 4; ++i) {
        int n = n0 + ty + i * 8;
        float v = t[tx][ty + i * 8];
        __nv_bfloat16 h = __float2bfloat16(v);
        __nv_bfloat16 l = __float2bfloat16(v - __bfloat162float(h));
        oh[(size_t)n * K + k0 + tx] = h;
        ol[(size_t)n * K + k0 + tx] = l;
    }
}

// ---------------------------------------------------------------------------
// V transpose: fp32 V[B,S,KVDIM] -> bf16 hi/lo Vt[B,G,HDIM,SEQ]
// ---------------------------------------------------------------------------
__global__ void vtrans_hilo(const float* __restrict__ V,
                            __nv_bfloat16* __restrict__ oh,
                            __nv_bfloat16* __restrict__ ol)
{
    __shared__ float t[32][33];
    int s0 = blockIdx.x * 32;
    int d0 = blockIdx.y * 32;     // index within KVDIM
    int b  = blockIdx.z;
    int tx = threadIdx.x, ty = threadIdx.y;
#pragma unroll
    for (int i = 0; i < 4; ++i) {
        int s = s0 + ty + i * 8;
        t[ty + i * 8][tx] = V[((size_t)b * SEQ + s) * KVDIM + d0 + tx];
    }
    __syncthreads();
#pragma unroll
    for (int i = 0; i < 4; ++i) {
        int d = d0 + ty + i * 8;
        int g = d >> 6, dd = d & 63;
        float v = t[tx][ty + i * 8];       // = V[b][s0+tx][d]
        __nv_bfloat16 h = __float2bfloat16(v);
        __nv_bfloat16 l = __float2bfloat16(v - __bfloat162float(h));
        size_t o = (((size_t)b * NGROUPS + g) * HDIM + dd) * SEQ + s0 + tx;
        oh[o] = h;
        ol[o] = l;
    }
}

// ---------------------------------------------------------------------------
// HMMA GEMM (unchanged from R12 pass), 3-term hi/lo split.
// ---------------------------------------------------------------------------
#define BM 128
#define BN 256
#define BKK 32
#define ASTRIDE 40
#define ABUF (BM * ASTRIDE)
#define BBUF (BN * ASTRIDE)
#define BUFU (ABUF + BBUF)
#define KSTEPS (GK / BKK)
#define NT (3 * KSTEPS)

__global__ __launch_bounds__(256)
void gemm_hmma(const __nv_bfloat16* __restrict__ Ah, const __nv_bfloat16* __restrict__ Al,
               const __nv_bfloat16* __restrict__ Bh, const __nv_bfloat16* __restrict__ Bl,
               float* __restrict__ C, int N, const float* __restrict__ bias)
{
    extern __shared__ __nv_bfloat16 sm[];

    const int tid  = threadIdx.x;
    const int wid  = tid >> 5;
    const int lane = tid & 31;
    const int m0   = blockIdx.y * BM;
    const int n0   = blockIdx.x * BN;
    const int wm0  = (wid & 1) * 64;
    const int wn0  = (wid >> 1) * 64;

    const __nv_bfloat16* Aop[3] = {Ah, Al, Ah};
    const __nv_bfloat16* Bop[3] = {Bh, Bh, Bl};

    const uint32_t sbase = smem_u32(sm);

    float acc[4][8][4];
#pragma unroll
    for (int i = 0; i < 4; ++i)
#pragma unroll
        for (int j = 0; j < 8; ++j)
#pragma unroll
            for (int k = 0; k < 4; ++k) acc[i][j][k] = 0.0f;

    const int ar = tid >> 2;
    const int ac = tid & 3;

    uint4 pa[2], pb[4];
    auto prefetch = [&](int p, int k0) {
        const __nv_bfloat16* A = Aop[p];
        const __nv_bfloat16* B = Bop[p];
        pa[0] = *(const uint4*)(A + (size_t)(m0 + ar) * GK + k0 + ac * 8);
        pa[1] = *(const uint4*)(A + (size_t)(m0 + ar + 64) * GK + k0 + ac * 8);
#pragma unroll
        for (int i = 0; i < 4; ++i)
            pb[i] = *(const uint4*)(B + (size_t)(n0 + ar + i * 64) * GK + k0 + ac * 8);
    };
    auto commit = [&](int buf) {
        __nv_bfloat16* s = sm + buf * BUFU;
        *(uint4*)(s + ar * ASTRIDE + ac * 8)        = pa[0];
        *(uint4*)(s + (ar + 64) * ASTRIDE + ac * 8) = pa[1];
        __nv_bfloat16* sb = s + ABUF;
#pragma unroll
        for (int i = 0; i < 4; ++i)
            *(uint4*)(sb + (ar + i * 64) * ASTRIDE + ac * 8) = pb[i];
    };

    const int aRow = lane & 15;
    const int aK   = ((lane >> 4) & 1) * 8;
    const int bRow = (lane & 7) | ((lane & 16) >> 1);
    const int bK   = lane & 8;

    prefetch(0, 0);
    commit(0);
    __syncthreads();

    for (int t = 0; t < NT; ++t) {
        const int cur = t & 1;
        if (t + 1 < NT) {
            const int tn = t + 1;
            prefetch(tn >> 6, (tn & (KSTEPS - 1)) * BKK);
        }
        const uint32_t sA = sbase + cur * (BUFU * 2);
        const uint32_t sB = sA + ABUF * 2;

#pragma unroll
        for (int kk = 0; kk < 2; ++kk) {
            uint32_t a[4][4];
#pragma unroll
            for (int mt = 0; mt < 4; ++mt)
                ldmx4(sA + (uint32_t)(((wm0 + mt * 16 + aRow) * ASTRIDE + kk * 16 + aK) * 2),
                      a[mt][0], a[mt][1], a[mt][2], a[mt][3]);
#pragma unroll
            for (int nt = 0; nt < 4; ++nt) {
                uint32_t b0, b1, b2, b3;
                ldmx4(sB + (uint32_t)(((wn0 + nt * 16 + bRow) * ASTRIDE + kk * 16 + bK) * 2),
                      b0, b1, b2, b3);
#pragma unroll
                for (int mt = 0; mt < 4; ++mt) {
                    mma16816(acc[mt][2 * nt + 0], a[mt], b0, b1);
                    mma16816(acc[mt][2 * nt + 1], a[mt], b2, b3);
                }
            }
        }
        if (t + 1 < NT) commit((t + 1) & 1);
        __syncthreads();
    }

    const int g  = lane >> 2;
    const int tq = lane & 3;
#pragma unroll
    for (int mt = 0; mt < 4; ++mt) {
#pragma unroll
        for (int n8 = 0; n8 < 8; ++n8) {
            int r  = m0 + wm0 + mt * 16 + g;
            int cc = n0 + wn0 + n8 * 8 + tq * 2;
            float2 v0 = make_float2(acc[mt][n8][0], acc[mt][n8][1]);
            float2 v1 = make_float2(acc[mt][n8][2], acc[mt][n8][3]);
            if (bias) {
                float2 bv = *(const float2*)(bias + cc);
                v0.x += bv.x; v0.y += bv.y;
                v1.x += bv.x; v1.y += bv.y;
            }
            *(float2*)(C + (size_t)r * N + cc)       = v0;
            *(float2*)(C + (size_t)(r + 8) * N + cc) = v1;
        }
    }
}

// ---------------------------------------------------------------------------
// Flash attention on HMMA (causal, GQA rep=4), 3-term hi/lo split throughout.
// CTA = (b, h, 128 q-rows); 8 warps x 16 rows; 64-key tiles, double-buffered.
// Q fragments (pre-scaled by 1/8) live in registers for the whole CTA.
// V is pre-transposed [B,G,D,S] so PV uses the same non-trans ldmatrix B path.
// ---------------------------------------------------------------------------
#define FSTR  72                  // bf16 units per smem row (144 B)
#define FSUB  (64 * FSTR)         // one 64-row subtile (units)
#define FSTAGE (4 * FSUB)         // Kh | Kl | Vh | Vl (units)

__global__ __launch_bounds__(256)
void flash_hmma(const __nv_bfloat16* __restrict__ Qh, const __nv_bfloat16* __restrict__ Ql,
                const __nv_bfloat16* __restrict__ Kh, const __nv_bfloat16* __restrict__ Kl,
                const __nv_bfloat16* __restrict__ Vh, const __nv_bfloat16* __restrict__ Vl,
                float* __restrict__ Ab)
{
    extern __shared__ __nv_bfloat16 fs[];

    const int qt = blockIdx.x;            // 0..15  (128-row q tile)
    const int h  = blockIdx.y;
    const int b  = blockIdx.z;
    const int g  = h >> 2;                // kv group
    const int tid = threadIdx.x, wid = tid >> 5, lane = tid & 31;
    const int q0 = qt * 128;
    const uint32_t sbase = smem_u32(fs);

    const int aRow = lane & 15;
    const int aK   = ((lane >> 4) & 1) * 8;
    const int bRow = (lane & 7) | ((lane & 16) >> 1);
    const int bK   = lane & 8;

    // ---- stage Q (hi at 0, lo at 128*FSTR) and load fragments ----
    {
        const __nv_bfloat16* qh = Qh + ((size_t)b * SEQ + q0) * EMB + h * HDIM;
        const __nv_bfloat16* ql = Ql + ((size_t)b * SEQ + q0) * EMB + h * HDIM;
#pragma unroll
        for (int i = 0; i < 4; ++i) {
            int id = i * 256 + tid;
            int r = id >> 3, c = id & 7;
            *(uint4*)(fs + r * FSTR + c * 8) =
                *(const uint4*)(qh + (size_t)r * EMB + c * 8);
            *(uint4*)(fs + 128 * FSTR + r * FSTR + c * 8) =
                *(const uint4*)(ql + (size_t)r * EMB + c * 8);
        }
    }
    __syncthreads();
    uint32_t qhf[4][4], qlf[4][4];
#pragma unroll
    for (int kk = 0; kk < 4; ++kk) {
        ldmx4(sbase + (uint32_t)(((16 * wid + aRow) * FSTR + kk * 16 + aK) * 2),
              qhf[kk][0], qhf[kk][1], qhf[kk][2], qhf[kk][3]);
        ldmx4(sbase + (uint32_t)((128 * FSTR + (16 * wid + aRow) * FSTR + kk * 16 + aK) * 2),
              qlf[kk][0], qlf[kk][1], qlf[kk][2], qlf[kk][3]);
    }
    __syncthreads();

    // ---- running state ----
    float oacc[8][4];
#pragma unroll
    for (int j = 0; j < 8; ++j)
#pragma unroll
        for (int k = 0; k < 4; ++k) oacc[j][k] = 0.0f;
    float m0v = -INFINITY, m1v = -INFINITY, l0v = 0.0f, l1v = 0.0f;

    // K/V global bases
    const __nv_bfloat16* khg = Kh + (size_t)b * SEQ * KVDIM + g * HDIM;
    const __nv_bfloat16* klg = Kl + (size_t)b * SEQ * KVDIM + g * HDIM;
    const __nv_bfloat16* vhg = Vh + ((size_t)b * NGROUPS + g) * HDIM * SEQ;
    const __nv_bfloat16* vlg = Vl + ((size_t)b * NGROUPS + g) * HDIM * SEQ;

    const int jrow = tid >> 2;      // 0..63 (key row for K, dim row for Vt)
    const int cch  = tid & 3;       // chunk base

    uint4 pkh[2], pkl[2], pvh[2], pvl[2];
    auto prefetch = [&](int k0) {
#pragma unroll
        for (int i = 0; i < 2; ++i) {
            int c = cch + i * 4;
            pkh[i] = *(const uint4*)(khg + (size_t)(k0 + jrow) * KVDIM + c * 8);
            pkl[i] = *(const uint4*)(klg + (size_t)(k0 + jrow) * KVDIM + c * 8);
            pvh[i] = *(const uint4*)(vhg + (size_t)jrow * SEQ + k0 + c * 8);
            pvl[i] = *(const uint4*)(vlg + (size_t)jrow * SEQ + k0 + c * 8);
        }
    };
    auto commit = [&](int buf) {
        __nv_bfloat16* d = fs + buf * FSTAGE;
#pragma unroll
        for (int i = 0; i < 2; ++i) {
            int c = cch + i * 4;
            *(uint4*)(d + jrow * FSTR + c * 8)            = pkh[i];
            *(uint4*)(d + FSUB + jrow * FSTR + c * 8)     = pkl[i];
            *(uint4*)(d + 2 * FSUB + jrow * FSTR + c * 8) = pvh[i];
            *(uint4*)(d + 3 * FSUB + jrow * FSTR + c * 8) = pvl[i];
        }
    };

    const int nkt = 2 * qt + 2;
    prefetch(0);
    commit(0);
    __syncthreads();

    for (int kt = 0; kt < nkt; ++kt) {
        const int k0 = kt * 64;
        const int cur = kt & 1;
        if (kt + 1 < nkt) prefetch((kt + 1) * 64);

        const bool active = (k0 <= q0 + 16 * wid + 15);
        if (active) {
            const uint32_t khB = sbase + (uint32_t)(cur * FSTAGE * 2);
            const uint32_t klB = khB + FSUB * 2;
            const uint32_t vhB = khB + 2 * FSUB * 2;
            const uint32_t vlB = khB + 3 * FSUB * 2;

            // ---- S = Q K^T (3-term) ----
            float sacc[8][4];
#pragma unroll
            for (int j = 0; j < 8; ++j)
#pragma unroll
                for (int k = 0; k < 4; ++k) sacc[j][k] = 0.0f;

#pragma unroll
            for (int kk = 0; kk < 4; ++kk) {
#pragma unroll
                for (int nt = 0; nt < 4; ++nt) {
                    uint32_t b0, b1, b2, b3, c0, c1, c2, c3;
                    ldmx4(khB + (uint32_t)(((nt * 16 + bRow) * FSTR + kk * 16 + bK) * 2),
                          b0, b1, b2, b3);
                    ldmx4(klB + (uint32_t)(((nt * 16 + bRow) * FSTR + kk * 16 + bK) * 2),
                          c0, c1, c2, c3);
                    mma16816(sacc[2 * nt + 0], qhf[kk], b0, b1);
                    mma16816(sacc[2 * nt + 1], qhf[kk], b2, b3);
                    mma16816(sacc[2 * nt + 0], qlf[kk], b0, b1);
                    mma16816(sacc[2 * nt + 1], qlf[kk], b2, b3);
                    mma16816(sacc[2 * nt + 0], qhf[kk], c0, c1);
                    mma16816(sacc[2 * nt + 1], qhf[kk], c2, c3);
                }
            }

            // ---- causal mask (only the last two tiles can be partial) ----
            const int r0 = q0 + 16 * wid + (lane >> 2);
            if (k0 + 63 > q0 + 16 * wid) {
#pragma unroll
                for (int j = 0; j < 8; ++j) {
                    int kc = k0 + j * 8 + (lane & 3) * 2;
                    if (kc     > r0)     sacc[j][0] = -INFINITY;
                    if (kc + 1 > r0)     sacc[j][1] = -INFINITY;
                    if (kc     > r0 + 8) sacc[j][2] = -INFINITY;
                    if (kc + 1 > r0 + 8) sacc[j][3] = -INFINITY;
                }
            }

            // ---- online softmax on fragments ----
            float mx0 = -INFINITY, mx1 = -INFINITY;
#pragma unroll
            for (int j = 0; j < 8; ++j) {
                mx0 = fmaxf(mx0, fmaxf(sacc[j][0], sacc[j][1]));
                mx1 = fmaxf(mx1, fmaxf(sacc[j][2], sacc[j][3]));
            }
#pragma unroll
            for (int off = 1; off <= 2; off <<= 1) {
                mx0 = fmaxf(mx0, __shfl_xor_sync(0xffffffffu, mx0, off));
                mx1 = fmaxf(mx1, __shfl_xor_sync(0xffffffffu, mx1, off));
            }
            float mn0 = fmaxf(m0v, mx0), mn1 = fmaxf(m1v, mx1);
            float al0 = __expf(m0v - mn0), al1 = __expf(m1v - mn1);
            m0v = mn0; m1v = mn1;

            uint32_t pah[4][4], pal[4][4];
            float rs0 = 0.0f, rs1 = 0.0f;
#pragma unroll
            for (int t = 0; t < 4; ++t) {
#pragma unroll
                for (int half = 0; half < 2; ++half) {
                    int j = 2 * t + half;
                    float p00 = __expf(sacc[j][0] - mn0);
                    float p01 = __expf(sacc[j][1] - mn0);
                    float p10 = __expf(sacc[j][2] - mn1);
                    float p11 = __expf(sacc[j][3] - mn1);
                    rs0 += p00 + p01;
                    rs1 += p10 + p11;
                    __nv_bfloat16 h00 = __float2bfloat16(p00);
                    __nv_bfloat16 h01 = __float2bfloat16(p01);
                    __nv_bfloat16 h10 = __float2bfloat16(p10);
                    __nv_bfloat16 h11 = __float2bfloat16(p11);
                    pah[t][0 + half * 2] = packbf(h00, h01);
                    pah[t][1 + half * 2] = packbf(h10, h11);
                    pal[t][0 + half * 2] = packbf(
                        __float2bfloat16(p00 - __bfloat162float(h00)),
                        __float2bfloat16(p01 - __bfloat162float(h01)));
                    pal[t][1 + half * 2] = packbf(
                        __float2bfloat16(p10 - __bfloat162float(h10)),
                        __float2bfloat16(p11 - __bfloat162float(h11)));
                }
            }
#pragma unroll
            for (int off = 1; off <= 2; off <<= 1) {
                rs0 += __shfl_xor_sync(0xffffffffu, rs0, off);
                rs1 += __shfl_xor_sync(0xffffffffu, rs1, off);
            }
            l0v = l0v * al0 + rs0;
            l1v = l1v * al1 + rs1;

            // rescale O
#pragma unroll
            for (int j = 0; j < 8; ++j) {
                oacc[j][0] *= al0; oacc[j][1] *= al0;
                oacc[j][2] *= al1; oacc[j][3] *= al1;
            }

            // ---- O += P V (3-term) ----
#pragma unroll
            for (int t = 0; t < 4; ++t) {
#pragma unroll
                for (int nt = 0; nt < 4; ++nt) {
                    uint32_t v0, v1, v2, v3, w0, w1, w2, w3;
                    ldmx4(vhB + (uint32_t)(((nt * 16 + bRow) * FSTR + t * 16 + bK) * 2),
                          v0, v1, v2, v3);
                    ldmx4(vlB + (uint32_t)(((nt * 16 + bRow) * FSTR + t * 16 + bK) * 2),
                          w0, w1, w2, w3);
                    mma16816(oacc[2 * nt + 0], pah[t], v0, v1);
                    mma16816(oacc[2 * nt + 1], pah[t], v2, v3);
                    mma16816(oacc[2 * nt + 0], pal[t], v0, v1);
                    mma16816(oacc[2 * nt + 1], pal[t], v2, v3);
                    mma16816(oacc[2 * nt + 0], pah[t], w0, w1);
                    mma16816(oacc[2 * nt + 1], pah[t], w2, w3);
                }
            }
        }

        if (kt + 1 < nkt) commit((kt + 1) & 1);
        __syncthreads();
    }

    // ---- finalize and store ----
    float i0 = 1.0f / l0v, i1 = 1.0f / l1v;
    float* out = Ab + ((size_t)b * SEQ + q0 + 16 * wid + (lane >> 2)) * EMB + h * HDIM;
#pragma unroll
    for (int j = 0; j < 8; ++j) {
        int col = j * 8 + (lane & 3) * 2;
        *(float2*)(out + col)           = make_float2(oacc[j][0] * i0, oacc[j][1] * i0);
        *(float2*)(out + 8 * EMB + col) = make_float2(oacc[j][2] * i1, oacc[j][3] * i1);
    }
}

// ---------------------------------------------------------------------------
// Launch
// ---------------------------------------------------------------------------
extern "C" void kernel_launch(void* const* d_in, const int* in_sizes, int n_in,
                              void* d_out, int out_size)
{
    const float* x  = (const float*)d_in[0];
    const float* Wq = (const float*)d_in[1];
    const float* Wk = (const float*)d_in[2];
    const float* Wv = (const float*)d_in[3];
    const float* Wo = (const float*)d_in[4];
    const float* bo = (const float*)d_in[5];
    float* out = (float*)d_out;

    float *Qp, *Kp, *Vp, *Ap;
    cudaGetSymbolAddress((void**)&Qp, g_Q);
    cudaGetSymbolAddress((void**)&Kp, g_K);
    cudaGetSymbolAddress((void**)&Vp, g_V);
    cudaGetSymbolAddress((void**)&Ap, g_A);

    __nv_bfloat16 *xh, *xl, *ah, *al;
    __nv_bfloat16 *wqh, *wql, *wkh, *wkl, *wvh, *wvl, *woh, *wol;
    __nv_bfloat16 *qh, *ql, *kh, *kl, *vth, *vtl;
    cudaGetSymbolAddress((void**)&xh, g_xh);   cudaGetSymbolAddress((void**)&xl, g_xl);
    cudaGetSymbolAddress((void**)&ah, g_ah);   cudaGetSymbolAddress((void**)&al, g_al);
    cudaGetSymbolAddress((void**)&wqh, g_Wqh); cudaGetSymbolAddress((void**)&wql, g_Wql);
    cudaGetSymbolAddress((void**)&wkh, g_Wkh); cudaGetSymbolAddress((void**)&wkl, g_Wkl);
    cudaGetSymbolAddress((void**)&wvh, g_Wvh); cudaGetSymbolAddress((void**)&wvl, g_Wvl);
    cudaGetSymbolAddress((void**)&woh, g_Woh); cudaGetSymbolAddress((void**)&wol, g_Wol);
    cudaGetSymbolAddress((void**)&qh, g_qh);   cudaGetSymbolAddress((void**)&ql, g_ql);
    cudaGetSymbolAddress((void**)&kh, g_kh);   cudaGetSymbolAddress((void**)&kl, g_kl);
    cudaGetSymbolAddress((void**)&vth, g_vth); cudaGetSymbolAddress((void**)&vtl, g_vtl);

    const int SMEM_GEMM = 2 * (BUFU * 2);      // 61440 B
    cudaFuncSetAttribute(gemm_hmma, cudaFuncAttributeMaxDynamicSharedMemorySize, SMEM_GEMM);
    const int SMEM_FLASH = 2 * FSTAGE * 2;     // 73728 B
    cudaFuncSetAttribute(flash_hmma, cudaFuncAttributeMaxDynamicSharedMemorySize, SMEM_FLASH);

    // 1. Convert x -> bf16 hi/lo
    {
        int n4 = ROWS * EMB / 4;
        convert_hilo<<<(n4 + 255) / 256, 256>>>(x, xh, xl, n4, 1.0f);
    }
    // 2. Transpose+convert weights -> [N,K] bf16 hi/lo
    transpose_hilo<<<dim3(EMB / 32,   EMB / 32), dim3(32, 8)>>>(Wq, wqh, wql, EMB, EMB);
    transpose_hilo<<<dim3(KVDIM / 32, EMB / 32), dim3(32, 8)>>>(Wk, wkh, wkl, EMB, KVDIM);
    transpose_hilo<<<dim3(KVDIM / 32, EMB / 32), dim3(32, 8)>>>(Wv, wvh, wvl, EMB, KVDIM);
    transpose_hilo<<<dim3(EMB / 32,   EMB / 32), dim3(32, 8)>>>(Wo, woh, wol, EMB, EMB);

    // 3. Projections on tensor cores (HMMA)
    gemm_hmma<<<dim3(EMB / BN,   ROWS / BM), 256, SMEM_GEMM>>>(xh, xl, wqh, wql, Qp, EMB,   nullptr);
    gemm_hmma<<<dim3(KVDIM / BN, ROWS / BM), 256, SMEM_GEMM>>>(xh, xl, wkh, wkl, Kp, KVDIM, nullptr);
    gemm_hmma<<<dim3(KVDIM / BN, ROWS / BM), 256, SMEM_GEMM>>>(xh, xl, wvh, wvl, Vp, KVDIM, nullptr);

    // 4. Convert Q (scale folded), K; transpose V
    {
        int n4 = ROWS * EMB / 4;
        convert_hilo<<<(n4 + 255) / 256, 256>>>(Qp, qh, ql, n4, 0.125f);
        int k4 = ROWS * KVDIM / 4;
        convert_hilo<<<(k4 + 255) / 256, 256>>>(Kp, kh, kl, k4, 1.0f);
    }
    vtrans_hilo<<<dim3(SEQ / 32, KVDIM / 32, BATCH), dim3(32, 8)>>>(Vp, vth, vtl);

    // 5. Flash attention on HMMA
    flash_hmma<<<dim3(SEQ / 128, NHEADS, BATCH), 256, SMEM_FLASH>>>(qh, ql, kh, kl, vth, vtl, Ap);

    // 6. attn -> bf16 hi/lo, output projection + bias
    {
        int n4 = ROWS * EMB / 4;
        convert_hilo<<<(n4 + 255) / 256, 256>>>(Ap, ah, al, n4, 1.0f);
    }
    gemm_hmma<<<dim3(EMB / BN, ROWS / BM), 256, SMEM_GEMM>>>(ah, al, woh, wol, out, EMB, bo);
}

// round 14
// speedup vs baseline: 2.4419x; 1.2355x over previous
#include <cuda_runtime.h>
#include <cuda_bf16.h>
#include <cstdint>
#include <math.h>

// Problem constants
#define BATCH   2
#define SEQ     2048
#define EMB     2048
#define NHEADS  32
#define NGROUPS 8
#define HDIM    64
#define KVDIM   (NGROUPS * HDIM)   // 512
#define ROWS    (BATCH * SEQ)      // 4096
#define GK      2048               // reduction dim for all GEMMs
#define NQKV    (EMB + 2 * KVDIM)  // 3072 fused output columns

// ---------------------------------------------------------------------------
// Scratch (no cudaMalloc allowed)
// ---------------------------------------------------------------------------
__device__ float g_V[(size_t)ROWS * KVDIM];     // fp32 V (for transpose)

__device__ __align__(16) __nv_bfloat16 g_xh[(size_t)ROWS * EMB];
__device__ __align__(16) __nv_bfloat16 g_xl[(size_t)ROWS * EMB];
__device__ __align__(16) __nv_bfloat16 g_ah[(size_t)ROWS * EMB];
__device__ __align__(16) __nv_bfloat16 g_al[(size_t)ROWS * EMB];
// Concatenated transposed weights [NQKV, GK] bf16 hi/lo (rows: Wq|Wk|Wv)
__device__ __align__(16) __nv_bfloat16 g_Wth[(size_t)NQKV * GK];
__device__ __align__(16) __nv_bfloat16 g_Wtl[(size_t)NQKV * GK];
__device__ __align__(16) __nv_bfloat16 g_Woh[(size_t)EMB * EMB], g_Wol[(size_t)EMB * EMB];
// flash operands
__device__ __align__(16) __nv_bfloat16 g_qh[(size_t)ROWS * EMB];
__device__ __align__(16) __nv_bfloat16 g_ql[(size_t)ROWS * EMB];
__device__ __align__(16) __nv_bfloat16 g_kh[(size_t)ROWS * KVDIM];
__device__ __align__(16) __nv_bfloat16 g_kl[(size_t)ROWS * KVDIM];
__device__ __align__(16) __nv_bfloat16 g_vth[(size_t)ROWS * KVDIM];
__device__ __align__(16) __nv_bfloat16 g_vtl[(size_t)ROWS * KVDIM];

// ---------------------------------------------------------------------------
// Primitives
// ---------------------------------------------------------------------------
__device__ __forceinline__ uint32_t smem_u32(const void* p) {
    uint32_t a;
    asm("{ .reg .u64 t; cvta.to.shared.u64 t, %1; cvt.u32.u64 %0, t; }"
        : "=r"(a) : "l"(p));
    return a;
}
__device__ __forceinline__ void ldmx4(uint32_t addr, uint32_t& r0, uint32_t& r1,
                                      uint32_t& r2, uint32_t& r3) {
    asm volatile("ldmatrix.sync.aligned.m8n8.x4.shared.b16 {%0,%1,%2,%3}, [%4];"
                 : "=r"(r0), "=r"(r1), "=r"(r2), "=r"(r3) : "r"(addr));
}
__device__ __forceinline__ void mma16816(float* c, const uint32_t* a,
                                         uint32_t b0, uint32_t b1) {
    asm volatile(
        "mma.sync.aligned.m16n8k16.row.col.f32.bf16.bf16.f32 "
        "{%0,%1,%2,%3}, {%4,%5,%6,%7}, {%8,%9}, {%0,%1,%2,%3};"
        : "+f"(c[0]), "+f"(c[1]), "+f"(c[2]), "+f"(c[3])
        : "r"(a[0]), "r"(a[1]), "r"(a[2]), "r"(a[3]), "r"(b0), "r"(b1));
}
__device__ __forceinline__ uint32_t packbf(__nv_bfloat16 a, __nv_bfloat16 b) {
    __nv_bfloat162 t = __halves2bfloat162(a, b);
    return *reinterpret_cast<uint32_t*>(&t);
}
__device__ __forceinline__ uint32_t hilo_h(float x, float y) {
    return packbf(__float2bfloat16(x), __float2bfloat16(y));
}
__device__ __forceinline__ uint32_t hilo_l(float x, float y) {
    __nv_bfloat16 hx = __float2bfloat16(x), hy = __float2bfloat16(y);
    return packbf(__float2bfloat16(x - __bfloat162float(hx)),
                  __float2bfloat16(y - __bfloat162float(hy)));
}
__device__ __forceinline__ void cp16(uint32_t dst, const void* src) {
    asm volatile("cp.async.cg.shared.global [%0], [%1], 16;" :: "r"(dst), "l"(src));
}
#define CP_COMMIT() asm volatile("cp.async.commit_group;" ::: "memory")
#define CP_WAIT2()  asm volatile("cp.async.wait_group 2;" ::: "memory")

// ---------------------------------------------------------------------------
// Conversion: fp32 [R,K] -> bf16 hi/lo [R,K]
// ---------------------------------------------------------------------------
__global__ void convert_hilo(const float* __restrict__ in,
                             __nv_bfloat16* __restrict__ oh,
                             __nv_bfloat16* __restrict__ ol, int n4, float scale)
{
    int idx = blockIdx.x * blockDim.x + threadIdx.x;
    if (idx >= n4) return;
    float4 v = ((const float4*)in)[idx];
    __nv_bfloat16 h[4], l[4];
    float f[4] = {v.x * scale, v.y * scale, v.z * scale, v.w * scale};
#pragma unroll
    for (int i = 0; i < 4; ++i) {
        h[i] = __float2bfloat16(f[i]);
        l[i] = __float2bfloat16(f[i] - __bfloat162float(h[i]));
    }
    ((uint2*)oh)[idx] = *(uint2*)h;
    ((uint2*)ol)[idx] = *(uint2*)l;
}

// ---------------------------------------------------------------------------
// Transpose + convert: fp32 [K,N] -> bf16 hi/lo [N,K]   (weights)
// ---------------------------------------------------------------------------
__global__ void transpose_hilo(const float* __restrict__ in,
                               __nv_bfloat16* __restrict__ oh,
                               __nv_bfloat16* __restrict__ ol, int K, int N)
{
    __shared__ float t[32][33];
    int n0 = blockIdx.x * 32;
    int k0 = blockIdx.y * 32;
    int tx = threadIdx.x, ty = threadIdx.y;
#pragma unroll
    for (int i = 0; i < 4; ++i) {
        int k = k0 + ty + i * 8;
        t[ty + i * 8][tx] = in[(size_t)k * N + n0 + tx];
    }
    __syncthreads();
#pragma unroll
    for (int i = 0; i < 4; ++i) {
        int n = n0 + ty + i * 8;
        float v = t[tx][ty + i * 8];
        __nv_bfloat16 h = __float2bfloat16(v);
        __nv_bfloat16 l = __float2bfloat16(v - __bfloat162float(h));
        oh[(size_t)n * K + k0 + tx] = h;
        ol[(size_t)n * K + k0 + tx] = l;
    }
}

// ---------------------------------------------------------------------------
// V transpose: fp32 V[B,S,KVDIM] -> bf16 hi/lo Vt[B,G,HDIM,SEQ]
// ---------------------------------------------------------------------------
__global__ void vtrans_hilo(const float* __restrict__ V,
                            __nv_bfloat16* __restrict__ oh,
                            __nv_bfloat16* __restrict__ ol)
{
    __shared__ float t[32][33];
    int s0 = blockIdx.x * 32;
    int d0 = blockIdx.y * 32;
    int b  = blockIdx.z;
    int tx = threadIdx.x, ty = threadIdx.y;
#pragma unroll
    for (int i = 0; i < 4; ++i) {
        int s = s0 + ty + i * 8;
        t[ty + i * 8][tx] = V[((size_t)b * SEQ + s) * KVDIM + d0 + tx];
    }
    __syncthreads();
#pragma unroll
    for (int i = 0; i < 4; ++i) {
        int d = d0 + ty + i * 8;
        int g = d >> 6, dd = d & 63;
        float v = t[tx][ty + i * 8];
        __nv_bfloat16 h = __float2bfloat16(v);
        __nv_bfloat16 l = __float2bfloat16(v - __bfloat162float(h));
        size_t o = (((size_t)b * NGROUPS + g) * HDIM + dd) * SEQ + s0 + tx;
        oh[o] = h;
        ol[o] = l;
    }
}

// ---------------------------------------------------------------------------
// HMMA GEMM, 3-term hi/lo split, 4-stage cp.async pipeline.
// QKV=0: C = A@B^T + bias (fp32 out).   QKV=1: fused epilogue routing:
//   cols [0,2048)    -> qh/ql  (x0.125, bf16 hi/lo)
//   cols [2048,2560) -> kh/kl  (bf16 hi/lo)
//   cols [2560,3072) -> vf     (fp32)
// ---------------------------------------------------------------------------
#define BM 128
#define BN 256
#define BKK 32
#define ASTRIDE 40
#define ABUF (BM * ASTRIDE)
#define BBUF (BN * ASTRIDE)
#define BUFU (ABUF + BBUF)            // 15360 units = 30720 B per stage
#define KSTEPS (GK / BKK)             // 64
#define NT (3 * KSTEPS)               // 192
#define NSTAGE 4
#define SMEM_GEMM (NSTAGE * BUFU * 2) // 122880 B

template <int QKV>
__global__ __launch_bounds__(256)
void gemm_cp(const __nv_bfloat16* __restrict__ Ah, const __nv_bfloat16* __restrict__ Al,
             const __nv_bfloat16* __restrict__ Bh, const __nv_bfloat16* __restrict__ Bl,
             float* __restrict__ C, int N, const float* __restrict__ bias,
             __nv_bfloat16* __restrict__ qh, __nv_bfloat16* __restrict__ ql,
             __nv_bfloat16* __restrict__ kh, __nv_bfloat16* __restrict__ kl,
             float* __restrict__ vf)
{
    extern __shared__ __nv_bfloat16 sm[];

    const int tid  = threadIdx.x;
    const int wid  = tid >> 5;
    const int lane = tid & 31;
    const int m0   = blockIdx.y * BM;
    const int n0   = blockIdx.x * BN;
    const int wm0  = (wid & 1) * 64;
    const int wn0  = (wid >> 1) * 64;

    const __nv_bfloat16* Aop[3] = {Ah, Al, Ah};
    const __nv_bfloat16* Bop[3] = {Bh, Bh, Bl};

    const uint32_t sbase = smem_u32(sm);

    float acc[4][8][4];
#pragma unroll
    for (int i = 0; i < 4; ++i)
#pragma unroll
        for (int j = 0; j < 8; ++j)
#pragma unroll
            for (int k = 0; k < 4; ++k) acc[i][j][k] = 0.0f;

    const int ar = tid >> 2;
    const int ac = tid & 3;

    auto issue = [&](int t, int buf) {
        const int p  = t >> 6;
        const int k0 = (t & (KSTEPS - 1)) * BKK;
        const __nv_bfloat16* A = Aop[p];
        const __nv_bfloat16* B = Bop[p];
        uint32_t sd  = sbase + (uint32_t)buf * (BUFU * 2);
        cp16(sd + (uint32_t)((ar * ASTRIDE + ac * 8) * 2),
             A + (size_t)(m0 + ar) * GK + k0 + ac * 8);
        cp16(sd + (uint32_t)(((ar + 64) * ASTRIDE + ac * 8) * 2),
             A + (size_t)(m0 + ar + 64) * GK + k0 + ac * 8);
        uint32_t sdb = sd + ABUF * 2;
#pragma unroll
        for (int i = 0; i < 4; ++i)
            cp16(sdb + (uint32_t)(((ar + i * 64) * ASTRIDE + ac * 8) * 2),
                 B + (size_t)(n0 + ar + i * 64) * GK + k0 + ac * 8);
    };

    const int aRow = lane & 15;
    const int aK   = ((lane >> 4) & 1) * 8;
    const int bRow = (lane & 7) | ((lane & 16) >> 1);
    const int bK   = lane & 8;

    // prologue: 3 stages in flight
#pragma unroll
    for (int s = 0; s < 3; ++s) { issue(s, s); CP_COMMIT(); }

    for (int t = 0; t < NT; ++t) {
        CP_WAIT2();
        __syncthreads();
        {
            int tn = t + 3;
            if (tn < NT) issue(tn, tn & 3);
            CP_COMMIT();
        }
        const uint32_t sA = sbase + (uint32_t)(t & 3) * (BUFU * 2);
        const uint32_t sB = sA + ABUF * 2;
#pragma unroll
        for (int kk = 0; kk < 2; ++kk) {
            uint32_t a[4][4];
#pragma unroll
            for (int mt = 0; mt < 4; ++mt)
                ldmx4(sA + (uint32_t)(((wm0 + mt * 16 + aRow) * ASTRIDE + kk * 16 + aK) * 2),
                      a[mt][0], a[mt][1], a[mt][2], a[mt][3]);
#pragma unroll
            for (int nt = 0; nt < 4; ++nt) {
                uint32_t b0, b1, b2, b3;
                ldmx4(sB + (uint32_t)(((wn0 + nt * 16 + bRow) * ASTRIDE + kk * 16 + bK) * 2),
                      b0, b1, b2, b3);
#pragma unroll
                for (int mt = 0; mt < 4; ++mt) {
                    mma16816(acc[mt][2 * nt + 0], a[mt], b0, b1);
                    mma16816(acc[mt][2 * nt + 1], a[mt], b2, b3);
                }
            }
        }
    }

    // ---------------- epilogue ----------------
    const int g  = lane >> 2;
    const int tq = lane & 3;

    if (QKV == 0) {
#pragma unroll
        for (int mt = 0; mt < 4; ++mt) {
#pragma unroll
            for (int n8 = 0; n8 < 8; ++n8) {
                int r  = m0 + wm0 + mt * 16 + g;
                int cc = n0 + wn0 + n8 * 8 + tq * 2;
                float2 v0 = make_float2(acc[mt][n8][0], acc[mt][n8][1]);
                float2 v1 = make_float2(acc[mt][n8][2], acc[mt][n8][3]);
                if (bias) {
                    float2 bv = *(const float2*)(bias + cc);
                    v0.x += bv.x; v0.y += bv.y;
                    v1.x += bv.x; v1.y += bv.y;
                }
                *(float2*)(C + (size_t)r * N + cc)       = v0;
                *(float2*)(C + (size_t)(r + 8) * N + cc) = v1;
            }
        }
    } else {
        // region routing (per-CTA: BN=256 tiles never straddle 2048/2560)
        __nv_bfloat16 *oh, *ol;
        float scale = 1.0f;
        int colbase, outw;
        bool isf32 = false;
        if (n0 < EMB)             { oh = qh; ol = ql; colbase = n0;              outw = EMB;   scale = 0.125f; }
        else if (n0 < EMB + KVDIM){ oh = kh; ol = kl; colbase = n0 - EMB;        outw = KVDIM; }
        else                      { oh = nullptr; ol = nullptr; colbase = n0 - EMB - KVDIM; outw = KVDIM; isf32 = true; }

#pragma unroll
        for (int mt = 0; mt < 4; ++mt) {
#pragma unroll
            for (int n8 = 0; n8 < 8; ++n8) {
                int r  = m0 + wm0 + mt * 16 + g;
                int cc = colbase + wn0 + n8 * 8 + tq * 2;
                float x0 = acc[mt][n8][0] * scale, x1 = acc[mt][n8][1] * scale;
                float y0 = acc[mt][n8][2] * scale, y1 = acc[mt][n8][3] * scale;
                if (isf32) {
                    *(float2*)(vf + (size_t)r * outw + cc)       = make_float2(x0, x1);
                    *(float2*)(vf + (size_t)(r + 8) * outw + cc) = make_float2(y0, y1);
                } else {
                    *(uint32_t*)(oh + (size_t)r * outw + cc)       = hilo_h(x0, x1);
                    *(uint32_t*)(ol + (size_t)r * outw + cc)       = hilo_l(x0, x1);
                    *(uint32_t*)(oh + (size_t)(r + 8) * outw + cc) = hilo_h(y0, y1);
                    *(uint32_t*)(ol + (size_t)(r + 8) * outw + cc) = hilo_l(y0, y1);
                }
            }
        }
    }
}

// ---------------------------------------------------------------------------
// Flash attention on HMMA (causal, GQA rep=4), 3-term hi/lo split.
// Writes attn output directly as bf16 hi/lo (feeds the O projection).
// ---------------------------------------------------------------------------
#define FSTR  72
#define FSUB  (64 * FSTR)
#define FSTAGE (4 * FSUB)

__global__ __launch_bounds__(256)
void flash_hmma(const __nv_bfloat16* __restrict__ Qh, const __nv_bfloat16* __restrict__ Ql,
                const __nv_bfloat16* __restrict__ Kh, const __nv_bfloat16* __restrict__ Kl,
                const __nv_bfloat16* __restrict__ Vh, const __nv_bfloat16* __restrict__ Vl,
                __nv_bfloat16* __restrict__ Aoh, __nv_bfloat16* __restrict__ Aol)
{
    extern __shared__ __nv_bfloat16 fs[];

    const int qt = blockIdx.x;
    const int h  = blockIdx.y;
    const int b  = blockIdx.z;
    const int g  = h >> 2;
    const int tid = threadIdx.x, wid = tid >> 5, lane = tid & 31;
    const int q0 = qt * 128;
    const uint32_t sbase = smem_u32(fs);

    const int aRow = lane & 15;
    const int aK   = ((lane >> 4) & 1) * 8;
    const int bRow = (lane & 7) | ((lane & 16) >> 1);
    const int bK   = lane & 8;

    // ---- stage Q and load fragments ----
    {
        const __nv_bfloat16* qh = Qh + ((size_t)b * SEQ + q0) * EMB + h * HDIM;
        const __nv_bfloat16* ql = Ql + ((size_t)b * SEQ + q0) * EMB + h * HDIM;
#pragma unroll
        for (int i = 0; i < 4; ++i) {
            int id = i * 256 + tid;
            int r = id >> 3, c = id & 7;
            *(uint4*)(fs + r * FSTR + c * 8) =
                *(const uint4*)(qh + (size_t)r * EMB + c * 8);
            *(uint4*)(fs + 128 * FSTR + r * FSTR + c * 8) =
                *(const uint4*)(ql + (size_t)r * EMB + c * 8);
        }
    }
    __syncthreads();
    uint32_t qhf[4][4], qlf[4][4];
#pragma unroll
    for (int kk = 0; kk < 4; ++kk) {
        ldmx4(sbase + (uint32_t)(((16 * wid + aRow) * FSTR + kk * 16 + aK) * 2),
              qhf[kk][0], qhf[kk][1], qhf[kk][2], qhf[kk][3]);
        ldmx4(sbase + (uint32_t)((128 * FSTR + (16 * wid + aRow) * FSTR + kk * 16 + aK) * 2),
              qlf[kk][0], qlf[kk][1], qlf[kk][2], qlf[kk][3]);
    }
    __syncthreads();

    float oacc[8][4];
#pragma unroll
    for (int j = 0; j < 8; ++j)
#pragma unroll
        for (int k = 0; k < 4; ++k) oacc[j][k] = 0.0f;
    float m0v = -INFINITY, m1v = -INFINITY, l0v = 0.0f, l1v = 0.0f;

    const __nv_bfloat16* khg = Kh + (size_t)b * SEQ * KVDIM + g * HDIM;
    const __nv_bfloat16* klg = Kl + (size_t)b * SEQ * KVDIM + g * HDIM;
    const __nv_bfloat16* vhg = Vh + ((size_t)b * NGROUPS + g) * HDIM * SEQ;
    const __nv_bfloat16* vlg = Vl + ((size_t)b * NGROUPS + g) * HDIM * SEQ;

    const int jrow = tid >> 2;
    const int cch  = tid & 3;

    uint4 pkh[2], pkl[2], pvh[2], pvl[2];
    auto prefetch = [&](int k0) {
#pragma unroll
        for (int i = 0; i < 2; ++i) {
            int c = cch + i * 4;
            pkh[i] = *(const uint4*)(khg + (size_t)(k0 + jrow) * KVDIM + c * 8);
            pkl[i] = *(const uint4*)(klg + (size_t)(k0 + jrow) * KVDIM + c * 8);
            pvh[i] = *(const uint4*)(vhg + (size_t)jrow * SEQ + k0 + c * 8);
            pvl[i] = *(const uint4*)(vlg + (size_t)jrow * SEQ + k0 + c * 8);
        }
    };
    auto commit = [&](int buf) {
        __nv_bfloat16* d = fs + buf * FSTAGE;
#pragma unroll
        for (int i = 0; i < 2; ++i) {
            int c = cch + i * 4;
            *(uint4*)(d + jrow * FSTR + c * 8)            = pkh[i];
            *(uint4*)(d + FSUB + jrow * FSTR + c * 8)     = pkl[i];
            *(uint4*)(d + 2 * FSUB + jrow * FSTR + c * 8) = pvh[i];
            *(uint4*)(d + 3 * FSUB + jrow * FSTR + c * 8) = pvl[i];
        }
    };

    const int nkt = 2 * qt + 2;
    prefetch(0);
    commit(0);
    __syncthreads();

    for (int kt = 0; kt < nkt; ++kt) {
        const int k0 = kt * 64;
        const int cur = kt & 1;
        if (kt + 1 < nkt) prefetch((kt + 1) * 64);

        const bool active = (k0 <= q0 + 16 * wid + 15);
        if (active) {
            const uint32_t khB = sbase + (uint32_t)(cur * FSTAGE * 2);
            const uint32_t klB = khB + FSUB * 2;
            const uint32_t vhB = khB + 2 * FSUB * 2;
            const uint32_t vlB = khB + 3 * FSUB * 2;

            float sacc[8][4];
#pragma unroll
            for (int j = 0; j < 8; ++j)
#pragma unroll
                for (int k = 0; k < 4; ++k) sacc[j][k] = 0.0f;

#pragma unroll
            for (int kk = 0; kk < 4; ++kk) {
#pragma unroll
                for (int nt = 0; nt < 4; ++nt) {
                    uint32_t b0, b1, b2, b3, c0, c1, c2, c3;
                    ldmx4(khB + (uint32_t)(((nt * 16 + bRow) * FSTR + kk * 16 + bK) * 2),
                          b0, b1, b2, b3);
                    ldmx4(klB + (uint32_t)(((nt * 16 + bRow) * FSTR + kk * 16 + bK) * 2),
                          c0, c1, c2, c3);
                    mma16816(sacc[2 * nt + 0], qhf[kk], b0, b1);
                    mma16816(sacc[2 * nt + 1], qhf[kk], b2, b3);
                    mma16816(sacc[2 * nt + 0], qlf[kk], b0, b1);
                    mma16816(sacc[2 * nt + 1], qlf[kk], b2, b3);
                    mma16816(sacc[2 * nt + 0], qhf[kk], c0, c1);
                    mma16816(sacc[2 * nt + 1], qhf[kk], c2, c3);
                }
            }

            const int r0 = q0 + 16 * wid + (lane >> 2);
            if (k0 + 63 > q0 + 16 * wid) {
#pragma unroll
                for (int j = 0; j < 8; ++j) {
                    int kc = k0 + j * 8 + (lane & 3) * 2;
                    if (kc     > r0)     sacc[j][0] = -INFINITY;
                    if (kc + 1 > r0)     sacc[j][1] = -INFINITY;
                    if (kc     > r0 + 8) sacc[j][2] = -INFINITY;
                    if (kc + 1 > r0 + 8) sacc[j][3] = -INFINITY;
                }
            }

            float mx0 = -INFINITY, mx1 = -INFINITY;
#pragma unroll
            for (int j = 0; j < 8; ++j) {
                mx0 = fmaxf(mx0, fmaxf(sacc[j][0], sacc[j][1]));
                mx1 = fmaxf(mx1, fmaxf(sacc[j][2], sacc[j][3]));
            }
#pragma unroll
            for (int off = 1; off <= 2; off <<= 1) {
                mx0 = fmaxf(mx0, __shfl_xor_sync(0xffffffffu, mx0, off));
                mx1 = fmaxf(mx1, __shfl_xor_sync(0xffffffffu, mx1, off));
            }
            float mn0 = fmaxf(m0v, mx0), mn1 = fmaxf(m1v, mx1);
            float al0 = __expf(m0v - mn0), al1 = __expf(m1v - mn1);
            m0v = mn0; m1v = mn1;

            uint32_t pah[4][4], pal[4][4];
            float rs0 = 0.0f, rs1 = 0.0f;
#pragma unroll
            for (int t = 0; t < 4; ++t) {
#pragma unroll
                for (int half = 0; half < 2; ++half) {
                    int j = 2 * t + half;
                    float p00 = __expf(sacc[j][0] - mn0);
                    float p01 = __expf(sacc[j][1] - mn0);
                    float p10 = __expf(sacc[j][2] - mn1);
                    float p11 = __expf(sacc[j][3] - mn1);
                    rs0 += p00 + p01;
                    rs1 += p10 + p11;
                    __nv_bfloat16 h00 = __float2bfloat16(p00);
                    __nv_bfloat16 h01 = __float2bfloat16(p01);
                    __nv_bfloat16 h10 = __float2bfloat16(p10);
                    __nv_bfloat16 h11 = __float2bfloat16(p11);
                    pah[t][0 + half * 2] = packbf(h00, h01);
                    pah[t][1 + half * 2] = packbf(h10, h11);
                    pal[t][0 + half * 2] = packbf(
                        __float2bfloat16(p00 - __bfloat162float(h00)),
                        __float2bfloat16(p01 - __bfloat162float(h01)));
                    pal[t][1 + half * 2] = packbf(
                        __float2bfloat16(p10 - __bfloat162float(h10)),
                        __float2bfloat16(p11 - __bfloat162float(h11)));
                }
            }
#pragma unroll
            for (int off = 1; off <= 2; off <<= 1) {
                rs0 += __shfl_xor_sync(0xffffffffu, rs0, off);
                rs1 += __shfl_xor_sync(0xffffffffu, rs1, off);
            }
            l0v = l0v * al0 + rs0;
            l1v = l1v * al1 + rs1;

#pragma unroll
            for (int j = 0; j < 8; ++j) {
                oacc[j][0] *= al0; oacc[j][1] *= al0;
                oacc[j][2] *= al1; oacc[j][3] *= al1;
            }

#pragma unroll
            for (int t = 0; t < 4; ++t) {
#pragma unroll
                for (int nt = 0; nt < 4; ++nt) {
                    uint32_t v0, v1, v2, v3, w0, w1, w2, w3;
                    ldmx4(vhB + (uint32_t)(((nt * 16 + bRow) * FSTR + t * 16 + bK) * 2),
                          v0, v1, v2, v3);
                    ldmx4(vlB + (uint32_t)(((nt * 16 + bRow) * FSTR + t * 16 + bK) * 2),
                          w0, w1, w2, w3);
                    mma16816(oacc[2 * nt + 0], pah[t], v0, v1);
                    mma16816(oacc[2 * nt + 1], pah[t], v2, v3);
                    mma16816(oacc[2 * nt + 0], pal[t], v0, v1);
                    mma16816(oacc[2 * nt + 1], pal[t], v2, v3);
                    mma16816(oacc[2 * nt + 0], pah[t], w0, w1);
                    mma16816(oacc[2 * nt + 1], pah[t], w2, w3);
                }
            }
        }

        if (kt + 1 < nkt) commit((kt + 1) & 1);
        __syncthreads();
    }

    // ---- finalize: write bf16 hi/lo attn output directly ----
    float i0 = 1.0f / l0v, i1 = 1.0f / l1v;
    size_t rowoff = ((size_t)b * SEQ + q0 + 16 * wid + (lane >> 2)) * EMB + h * HDIM;
    __nv_bfloat16* oh = Aoh + rowoff;
    __nv_bfloat16* ol = Aol + rowoff;
#pragma unroll
    for (int j = 0; j < 8; ++j) {
        int col = j * 8 + (lane & 3) * 2;
        float x0 = oacc[j][0] * i0, x1 = oacc[j][1] * i0;
        float y0 = oacc[j][2] * i1, y1 = oacc[j][3] * i1;
        *(uint32_t*)(oh + col)           = hilo_h(x0, x1);
        *(uint32_t*)(ol + col)           = hilo_l(x0, x1);
        *(uint32_t*)(oh + 8 * EMB + col) = hilo_h(y0, y1);
        *(uint32_t*)(ol + 8 * EMB + col) = hilo_l(y0, y1);
    }
}

// ---------------------------------------------------------------------------
// Launch
// ---------------------------------------------------------------------------
extern "C" void kernel_launch(void* const* d_in, const int* in_sizes, int n_in,
                              void* d_out, int out_size)
{
    const float* x  = (const float*)d_in[0];
    const float* Wq = (const float*)d_in[1];
    const float* Wk = (const float*)d_in[2];
    const float* Wv = (const float*)d_in[3];
    const float* Wo = (const float*)d_in[4];
    const float* bo = (const float*)d_in[5];
    float* out = (float*)d_out;

    float* Vp;
    cudaGetSymbolAddress((void**)&Vp, g_V);

    __nv_bfloat16 *xh, *xl, *ah, *al, *wth, *wtl, *woh, *wol;
    __nv_bfloat16 *qh, *ql, *kh, *kl, *vth, *vtl;
    cudaGetSymbolAddress((void**)&xh, g_xh);   cudaGetSymbolAddress((void**)&xl, g_xl);
    cudaGetSymbolAddress((void**)&ah, g_ah);   cudaGetSymbolAddress((void**)&al, g_al);
    cudaGetSymbolAddress((void**)&wth, g_Wth); cudaGetSymbolAddress((void**)&wtl, g_Wtl);
    cudaGetSymbolAddress((void**)&woh, g_Woh); cudaGetSymbolAddress((void**)&wol, g_Wol);
    cudaGetSymbolAddress((void**)&qh, g_qh);   cudaGetSymbolAddress((void**)&ql, g_ql);
    cudaGetSymbolAddress((void**)&kh, g_kh);   cudaGetSymbolAddress((void**)&kl, g_kl);
    cudaGetSymbolAddress((void**)&vth, g_vth); cudaGetSymbolAddress((void**)&vtl, g_vtl);

    cudaFuncSetAttribute(gemm_cp<0>, cudaFuncAttributeMaxDynamicSharedMemorySize, SMEM_GEMM);
    cudaFuncSetAttribute(gemm_cp<1>, cudaFuncAttributeMaxDynamicSharedMemorySize, SMEM_GEMM);
    const int SMEM_FLASH = 2 * FSTAGE * 2;     // 73728 B
    cudaFuncSetAttribute(flash_hmma, cudaFuncAttributeMaxDynamicSharedMemorySize, SMEM_FLASH);

    // 1. Convert x -> bf16 hi/lo
    {
        int n4 = ROWS * EMB / 4;
        convert_hilo<<<(n4 + 255) / 256, 256>>>(x, xh, xl, n4, 1.0f);
    }
    // 2. Transpose+convert weights into concatenated [NQKV, GK]; Wo separate
    transpose_hilo<<<dim3(EMB / 32,   EMB / 32), dim3(32, 8)>>>(Wq, wth, wtl, GK, EMB);
    transpose_hilo<<<dim3(KVDIM / 32, EMB / 32), dim3(32, 8)>>>(Wk, wth + (size_t)EMB * GK,
                                                                wtl + (size_t)EMB * GK, GK, KVDIM);
    transpose_hilo<<<dim3(KVDIM / 32, EMB / 32), dim3(32, 8)>>>(Wv, wth + (size_t)(EMB + KVDIM) * GK,
                                                                wtl + (size_t)(EMB + KVDIM) * GK, GK, KVDIM);
    transpose_hilo<<<dim3(EMB / 32,   EMB / 32), dim3(32, 8)>>>(Wo, woh, wol, GK, EMB);

    // 3. Fused QKV projection: epilogue writes qh/ql (x0.125), kh/kl, fp32 V
    gemm_cp<1><<<dim3(NQKV / BN, ROWS / BM), 256, SMEM_GEMM>>>(
        xh, xl, wth, wtl, nullptr, 0, nullptr, qh, ql, kh, kl, Vp);

    // 4. Transpose V -> bf16 hi/lo [B,G,D,S]
    vtrans_hilo<<<dim3(SEQ / 32, KVDIM / 32, BATCH), dim3(32, 8)>>>(Vp, vth, vtl);

    // 5. Flash attention (HMMA), writes ah/al directly
    flash_hmma<<<dim3(SEQ / 128, NHEADS, BATCH), 256, SMEM_FLASH>>>(
        qh, ql, kh, kl, vth, vtl, ah, al);

    // 6. Output projection + bias
    gemm_cp<0><<<dim3(EMB / BN, ROWS / BM), 256, SMEM_GEMM>>>(
        ah, al, woh, wol, out, EMB, bo, nullptr, nullptr, nullptr, nullptr, nullptr);
}

// round 15
// speedup vs baseline: 2.4426x; 1.0003x over previous
#include <cuda_runtime.h>
#include <cuda_bf16.h>
#include <cstdint>
#include <math.h>

// Problem constants
#define BATCH   2
#define SEQ     2048
#define EMB     2048
#define NHEADS  32
#define NGROUPS 8
#define HDIM    64
#define KVDIM   (NGROUPS * HDIM)   // 512
#define ROWS    (BATCH * SEQ)      // 4096
#define GK      2048               // reduction dim for all GEMMs
#define NQKV    (EMB + 2 * KVDIM)  // 3072 fused output columns

// ---------------------------------------------------------------------------
// Scratch (no cudaMalloc allowed)
// ---------------------------------------------------------------------------
__device__ float g_V[(size_t)ROWS * KVDIM];     // fp32 V (for transpose)

__device__ __align__(16) __nv_bfloat16 g_xh[(size_t)ROWS * EMB];
__device__ __align__(16) __nv_bfloat16 g_xl[(size_t)ROWS * EMB];
__device__ __align__(16) __nv_bfloat16 g_ah[(size_t)ROWS * EMB];
__device__ __align__(16) __nv_bfloat16 g_al[(size_t)ROWS * EMB];
// Concatenated transposed weights [NQKV, GK] bf16 hi/lo (rows: Wq|Wk|Wv)
__device__ __align__(16) __nv_bfloat16 g_Wth[(size_t)NQKV * GK];
__device__ __align__(16) __nv_bfloat16 g_Wtl[(size_t)NQKV * GK];
__device__ __align__(16) __nv_bfloat16 g_Woh[(size_t)EMB * EMB], g_Wol[(size_t)EMB * EMB];
// flash operands
__device__ __align__(16) __nv_bfloat16 g_qh[(size_t)ROWS * EMB];
__device__ __align__(16) __nv_bfloat16 g_ql[(size_t)ROWS * EMB];
__device__ __align__(16) __nv_bfloat16 g_kh[(size_t)ROWS * KVDIM];
__device__ __align__(16) __nv_bfloat16 g_kl[(size_t)ROWS * KVDIM];
__device__ __align__(16) __nv_bfloat16 g_vth[(size_t)ROWS * KVDIM];
__device__ __align__(16) __nv_bfloat16 g_vtl[(size_t)ROWS * KVDIM];

// ---------------------------------------------------------------------------
// Primitives
// ---------------------------------------------------------------------------
__device__ __forceinline__ uint32_t smem_u32(const void* p) {
    uint32_t a;
    asm("{ .reg .u64 t; cvta.to.shared.u64 t, %1; cvt.u32.u64 %0, t; }"
        : "=r"(a) : "l"(p));
    return a;
}
__device__ __forceinline__ void ldmx4(uint32_t addr, uint32_t& r0, uint32_t& r1,
                                      uint32_t& r2, uint32_t& r3) {
    asm volatile("ldmatrix.sync.aligned.m8n8.x4.shared.b16 {%0,%1,%2,%3}, [%4];"
                 : "=r"(r0), "=r"(r1), "=r"(r2), "=r"(r3) : "r"(addr));
}
__device__ __forceinline__ void mma16816(float* c, const uint32_t* a,
                                         uint32_t b0, uint32_t b1) {
    asm volatile(
        "mma.sync.aligned.m16n8k16.row.col.f32.bf16.bf16.f32 "
        "{%0,%1,%2,%3}, {%4,%5,%6,%7}, {%8,%9}, {%0,%1,%2,%3};"
        : "+f"(c[0]), "+f"(c[1]), "+f"(c[2]), "+f"(c[3])
        : "r"(a[0]), "r"(a[1]), "r"(a[2]), "r"(a[3]), "r"(b0), "r"(b1));
}
__device__ __forceinline__ uint32_t packbf(__nv_bfloat16 a, __nv_bfloat16 b) {
    __nv_bfloat162 t = __halves2bfloat162(a, b);
    return *reinterpret_cast<uint32_t*>(&t);
}
__device__ __forceinline__ uint32_t hilo_h(float x, float y) {
    return packbf(__float2bfloat16(x), __float2bfloat16(y));
}
__device__ __forceinline__ uint32_t hilo_l(float x, float y) {
    __nv_bfloat16 hx = __float2bfloat16(x), hy = __float2bfloat16(y);
    return packbf(__float2bfloat16(x - __bfloat162float(hx)),
                  __float2bfloat16(y - __bfloat162float(hy)));
}
__device__ __forceinline__ void cp16(uint32_t dst, const void* src) {
    asm volatile("cp.async.cg.shared.global [%0], [%1], 16;" :: "r"(dst), "l"(src));
}
#define CP_COMMIT() asm volatile("cp.async.commit_group;" ::: "memory")
#define CP_WAIT2()  asm volatile("cp.async.wait_group 2;" ::: "memory")

// ---------------------------------------------------------------------------
// Conversion: fp32 [R,K] -> bf16 hi/lo [R,K]
// ---------------------------------------------------------------------------
__global__ void convert_hilo(const float* __restrict__ in,
                             __nv_bfloat16* __restrict__ oh,
                             __nv_bfloat16* __restrict__ ol, int n4, float scale)
{
    int idx = blockIdx.x * blockDim.x + threadIdx.x;
    if (idx >= n4) return;
    float4 v = ((const float4*)in)[idx];
    __nv_bfloat16 h[4], l[4];
    float f[4] = {v.x * scale, v.y * scale, v.z * scale, v.w * scale};
#pragma unroll
    for (int i = 0; i < 4; ++i) {
        h[i] = __float2bfloat16(f[i]);
        l[i] = __float2bfloat16(f[i] - __bfloat162float(h[i]));
    }
    ((uint2*)oh)[idx] = *(uint2*)h;
    ((uint2*)ol)[idx] = *(uint2*)l;
}

// ---------------------------------------------------------------------------
// ALL weight transposes fused into one launch.
// grid = (GK/32, 160): y-tiles 0..63 -> Wq, 64..79 -> Wk, 80..95 -> Wv,
// 96..159 -> Wo.  fp32 [GK, N] -> bf16 hi/lo [N, GK] at the right offset.
// ---------------------------------------------------------------------------
__global__ void wtrans_all(const float* __restrict__ Wq, const float* __restrict__ Wk,
                           const float* __restrict__ Wv, const float* __restrict__ Wo,
                           __nv_bfloat16* __restrict__ wth, __nv_bfloat16* __restrict__ wtl,
                           __nv_bfloat16* __restrict__ woh, __nv_bfloat16* __restrict__ wol)
{
    __shared__ float t[32][33];
    const int yb = blockIdx.y;
    const float* in;
    __nv_bfloat16 *oh, *ol;
    int N, nt;
    if (yb < 64)       { in = Wq; oh = wth;                          ol = wtl;                          N = EMB;   nt = yb; }
    else if (yb < 80)  { in = Wk; oh = wth + (size_t)EMB * GK;       ol = wtl + (size_t)EMB * GK;       N = KVDIM; nt = yb - 64; }
    else if (yb < 96)  { in = Wv; oh = wth + (size_t)(EMB+KVDIM)*GK; ol = wtl + (size_t)(EMB+KVDIM)*GK; N = KVDIM; nt = yb - 80; }
    else               { in = Wo; oh = woh;                          ol = wol;                          N = EMB;   nt = yb - 96; }

    const int n0 = nt * 32;
    const int k0 = blockIdx.x * 32;
    const int tx = threadIdx.x, ty = threadIdx.y;
#pragma unroll
    for (int i = 0; i < 4; ++i) {
        int k = k0 + ty + i * 8;
        t[ty + i * 8][tx] = in[(size_t)k * N + n0 + tx];
    }
    __syncthreads();
#pragma unroll
    for (int i = 0; i < 4; ++i) {
        int n = n0 + ty + i * 8;
        float v = t[tx][ty + i * 8];
        __nv_bfloat16 h = __float2bfloat16(v);
        __nv_bfloat16 l = __float2bfloat16(v - __bfloat162float(h));
        oh[(size_t)n * GK + k0 + tx] = h;
        ol[(size_t)n * GK + k0 + tx] = l;
    }
}

// ---------------------------------------------------------------------------
// V transpose: fp32 V[B,S,KVDIM] -> bf16 hi/lo Vt[B,G,HDIM,SEQ]
// ---------------------------------------------------------------------------
__global__ void vtrans_hilo(const float* __restrict__ V,
                            __nv_bfloat16* __restrict__ oh,
                            __nv_bfloat16* __restrict__ ol)
{
    __shared__ float t[32][33];
    int s0 = blockIdx.x * 32;
    int d0 = blockIdx.y * 32;
    int b  = blockIdx.z;
    int tx = threadIdx.x, ty = threadIdx.y;
#pragma unroll
    for (int i = 0; i < 4; ++i) {
        int s = s0 + ty + i * 8;
        t[ty + i * 8][tx] = V[((size_t)b * SEQ + s) * KVDIM + d0 + tx];
    }
    __syncthreads();
#pragma unroll
    for (int i = 0; i < 4; ++i) {
        int d = d0 + ty + i * 8;
        int g = d >> 6, dd = d & 63;
        float v = t[tx][ty + i * 8];
        __nv_bfloat16 h = __float2bfloat16(v);
        __nv_bfloat16 l = __float2bfloat16(v - __bfloat162float(h));
        size_t o = (((size_t)b * NGROUPS + g) * HDIM + dd) * SEQ + s0 + tx;
        oh[o] = h;
        ol[o] = l;
    }
}

// ---------------------------------------------------------------------------
// HMMA GEMM, 3-term hi/lo split, 4-stage cp.async pipeline, fragment preload.
// QKV=0: C = A@B^T + bias (fp32 out).   QKV=1: fused epilogue routing.
// ---------------------------------------------------------------------------
#define BM 128
#define BN 256
#define BKK 32
#define ASTRIDE 40
#define ABUF (BM * ASTRIDE)
#define BBUF (BN * ASTRIDE)
#define BUFU (ABUF + BBUF)            // 15360 units = 30720 B per stage
#define KSTEPS (GK / BKK)             // 64
#define NT (3 * KSTEPS)               // 192
#define NSTAGE 4
#define SMEM_GEMM (NSTAGE * BUFU * 2) // 122880 B

template <int QKV>
__global__ __launch_bounds__(256)
void gemm_cp(const __nv_bfloat16* __restrict__ Ah, const __nv_bfloat16* __restrict__ Al,
             const __nv_bfloat16* __restrict__ Bh, const __nv_bfloat16* __restrict__ Bl,
             float* __restrict__ C, int N, const float* __restrict__ bias,
             __nv_bfloat16* __restrict__ qh, __nv_bfloat16* __restrict__ ql,
             __nv_bfloat16* __restrict__ kh, __nv_bfloat16* __restrict__ kl,
             float* __restrict__ vf)
{
    extern __shared__ __nv_bfloat16 sm[];

    const int tid  = threadIdx.x;
    const int wid  = tid >> 5;
    const int lane = tid & 31;
    const int m0   = blockIdx.y * BM;
    const int n0   = blockIdx.x * BN;
    const int wm0  = (wid & 1) * 64;
    const int wn0  = (wid >> 1) * 64;

    const __nv_bfloat16* Aop[3] = {Ah, Al, Ah};
    const __nv_bfloat16* Bop[3] = {Bh, Bh, Bl};

    const uint32_t sbase = smem_u32(sm);

    float acc[4][8][4];
#pragma unroll
    for (int i = 0; i < 4; ++i)
#pragma unroll
        for (int j = 0; j < 8; ++j)
#pragma unroll
            for (int k = 0; k < 4; ++k) acc[i][j][k] = 0.0f;

    const int ar = tid >> 2;
    const int ac = tid & 3;

    auto issue = [&](int t, int buf) {
        const int p  = t >> 6;
        const int k0 = (t & (KSTEPS - 1)) * BKK;
        const __nv_bfloat16* A = Aop[p];
        const __nv_bfloat16* B = Bop[p];
        uint32_t sd  = sbase + (uint32_t)buf * (BUFU * 2);
        cp16(sd + (uint32_t)((ar * ASTRIDE + ac * 8) * 2),
             A + (size_t)(m0 + ar) * GK + k0 + ac * 8);
        cp16(sd + (uint32_t)(((ar + 64) * ASTRIDE + ac * 8) * 2),
             A + (size_t)(m0 + ar + 64) * GK + k0 + ac * 8);
        uint32_t sdb = sd + ABUF * 2;
#pragma unroll
        for (int i = 0; i < 4; ++i)
            cp16(sdb + (uint32_t)(((ar + i * 64) * ASTRIDE + ac * 8) * 2),
                 B + (size_t)(n0 + ar + i * 64) * GK + k0 + ac * 8);
    };

    const int aRow = lane & 15;
    const int aK   = ((lane >> 4) & 1) * 8;
    const int bRow = (lane & 7) | ((lane & 16) >> 1);
    const int bK   = lane & 8;

    // prologue: 3 stages in flight
#pragma unroll
    for (int s = 0; s < 3; ++s) { issue(s, s); CP_COMMIT(); }

    for (int t = 0; t < NT; ++t) {
        CP_WAIT2();
        __syncthreads();
        {
            int tn = t + 3;
            if (tn < NT) issue(tn, tn & 3);
            CP_COMMIT();
        }
        const uint32_t sA = sbase + (uint32_t)(t & 3) * (BUFU * 2);
        const uint32_t sB = sA + ABUF * 2;

        // ---- preload ALL fragments for this k-step, then burst 128 MMAs ----
        uint32_t a[2][4][4], bf[2][4][4];
#pragma unroll
        for (int kk = 0; kk < 2; ++kk) {
#pragma unroll
            for (int mt = 0; mt < 4; ++mt)
                ldmx4(sA + (uint32_t)(((wm0 + mt * 16 + aRow) * ASTRIDE + kk * 16 + aK) * 2),
                      a[kk][mt][0], a[kk][mt][1], a[kk][mt][2], a[kk][mt][3]);
#pragma unroll
            for (int nt = 0; nt < 4; ++nt)
                ldmx4(sB + (uint32_t)(((wn0 + nt * 16 + bRow) * ASTRIDE + kk * 16 + bK) * 2),
                      bf[kk][nt][0], bf[kk][nt][1], bf[kk][nt][2], bf[kk][nt][3]);
        }
#pragma unroll
        for (int kk = 0; kk < 2; ++kk)
#pragma unroll
            for (int nt = 0; nt < 4; ++nt)
#pragma unroll
                for (int mt = 0; mt < 4; ++mt) {
                    mma16816(acc[mt][2 * nt + 0], a[kk][mt], bf[kk][nt][0], bf[kk][nt][1]);
                    mma16816(acc[mt][2 * nt + 1], a[kk][mt], bf[kk][nt][2], bf[kk][nt][3]);
                }
    }

    // ---------------- epilogue ----------------
    const int g  = lane >> 2;
    const int tq = lane & 3;

    if (QKV == 0) {
#pragma unroll
        for (int mt = 0; mt < 4; ++mt) {
#pragma unroll
            for (int n8 = 0; n8 < 8; ++n8) {
                int r  = m0 + wm0 + mt * 16 + g;
                int cc = n0 + wn0 + n8 * 8 + tq * 2;
                float2 v0 = make_float2(acc[mt][n8][0], acc[mt][n8][1]);
                float2 v1 = make_float2(acc[mt][n8][2], acc[mt][n8][3]);
                if (bias) {
                    float2 bv = *(const float2*)(bias + cc);
                    v0.x += bv.x; v0.y += bv.y;
                    v1.x += bv.x; v1.y += bv.y;
                }
                *(float2*)(C + (size_t)r * N + cc)       = v0;
                *(float2*)(C + (size_t)(r + 8) * N + cc) = v1;
            }
        }
    } else {
        __nv_bfloat16 *oh, *ol;
        float scale = 1.0f;
        int colbase, outw;
        bool isf32 = false;
        if (n0 < EMB)             { oh = qh; ol = ql; colbase = n0;              outw = EMB;   scale = 0.125f; }
        else if (n0 < EMB + KVDIM){ oh = kh; ol = kl; colbase = n0 - EMB;        outw = KVDIM; }
        else                      { oh = nullptr; ol = nullptr; colbase = n0 - EMB - KVDIM; outw = KVDIM; isf32 = true; }

#pragma unroll
        for (int mt = 0; mt < 4; ++mt) {
#pragma unroll
            for (int n8 = 0; n8 < 8; ++n8) {
                int r  = m0 + wm0 + mt * 16 + g;
                int cc = colbase + wn0 + n8 * 8 + tq * 2;
                float x0 = acc[mt][n8][0] * scale, x1 = acc[mt][n8][1] * scale;
                float y0 = acc[mt][n8][2] * scale, y1 = acc[mt][n8][3] * scale;
                if (isf32) {
                    *(float2*)(vf + (size_t)r * outw + cc)       = make_float2(x0, x1);
                    *(float2*)(vf + (size_t)(r + 8) * outw + cc) = make_float2(y0, y1);
                } else {
                    *(uint32_t*)(oh + (size_t)r * outw + cc)       = hilo_h(x0, x1);
                    *(uint32_t*)(ol + (size_t)r * outw + cc)       = hilo_l(x0, x1);
                    *(uint32_t*)(oh + (size_t)(r + 8) * outw + cc) = hilo_h(y0, y1);
                    *(uint32_t*)(ol + (size_t)(r + 8) * outw + cc) = hilo_l(y0, y1);
                }
            }
        }
    }
}

// ---------------------------------------------------------------------------
// Flash attention on HMMA (causal, GQA rep=4), 3-term hi/lo split.
// ---------------------------------------------------------------------------
#define FSTR  72
#define FSUB  (64 * FSTR)
#define FSTAGE (4 * FSUB)

__global__ __launch_bounds__(256)
void flash_hmma(const __nv_bfloat16* __restrict__ Qh, const __nv_bfloat16* __restrict__ Ql,
                const __nv_bfloat16* __restrict__ Kh, const __nv_bfloat16* __restrict__ Kl,
                const __nv_bfloat16* __restrict__ Vh, const __nv_bfloat16* __restrict__ Vl,
                __nv_bfloat16* __restrict__ Aoh, __nv_bfloat16* __restrict__ Aol)
{
    extern __shared__ __nv_bfloat16 fs[];

    const int qt = blockIdx.x;
    const int h  = blockIdx.y;
    const int b  = blockIdx.z;
    const int g  = h >> 2;
    const int tid = threadIdx.x, wid = tid >> 5, lane = tid & 31;
    const int q0 = qt * 128;
    const uint32_t sbase = smem_u32(fs);

    const int aRow = lane & 15;
    const int aK   = ((lane >> 4) & 1) * 8;
    const int bRow = (lane & 7) | ((lane & 16) >> 1);
    const int bK   = lane & 8;

    {
        const __nv_bfloat16* qh = Qh + ((size_t)b * SEQ + q0) * EMB + h * HDIM;
        const __nv_bfloat16* ql = Ql + ((size_t)b * SEQ + q0) * EMB + h * HDIM;
#pragma unroll
        for (int i = 0; i < 4; ++i) {
            int id = i * 256 + tid;
            int r = id >> 3, c = id & 7;
            *(uint4*)(fs + r * FSTR + c * 8) =
                *(const uint4*)(qh + (size_t)r * EMB + c * 8);
            *(uint4*)(fs + 128 * FSTR + r * FSTR + c * 8) =
                *(const uint4*)(ql + (size_t)r * EMB + c * 8);
        }
    }
    __syncthreads();
    uint32_t qhf[4][4], qlf[4][4];
#pragma unroll
    for (int kk = 0; kk < 4; ++kk) {
        ldmx4(sbase + (uint32_t)(((16 * wid + aRow) * FSTR + kk * 16 + aK) * 2),
              qhf[kk][0], qhf[kk][1], qhf[kk][2], qhf[kk][3]);
        ldmx4(sbase + (uint32_t)((128 * FSTR + (16 * wid + aRow) * FSTR + kk * 16 + aK) * 2),
              qlf[kk][0], qlf[kk][1], qlf[kk][2], qlf[kk][3]);
    }
    __syncthreads();

    float oacc[8][4];
#pragma unroll
    for (int j = 0; j < 8; ++j)
#pragma unroll
        for (int k = 0; k < 4; ++k) oacc[j][k] = 0.0f;
    float m0v = -INFINITY, m1v = -INFINITY, l0v = 0.0f, l1v = 0.0f;

    const __nv_bfloat16* khg = Kh + (size_t)b * SEQ * KVDIM + g * HDIM;
    const __nv_bfloat16* klg = Kl + (size_t)b * SEQ * KVDIM + g * HDIM;
    const __nv_bfloat16* vhg = Vh + ((size_t)b * NGROUPS + g) * HDIM * SEQ;
    const __nv_bfloat16* vlg = Vl + ((size_t)b * NGROUPS + g) * HDIM * SEQ;

    const int jrow = tid >> 2;
    const int cch  = tid & 3;

    uint4 pkh[2], pkl[2], pvh[2], pvl[2];
    auto prefetch = [&](int k0) {
#pragma unroll
        for (int i = 0; i < 2; ++i) {
            int c = cch + i * 4;
            pkh[i] = *(const uint4*)(khg + (size_t)(k0 + jrow) * KVDIM + c * 8);
            pkl[i] = *(const uint4*)(klg + (size_t)(k0 + jrow) * KVDIM + c * 8);
            pvh[i] = *(const uint4*)(vhg + (size_t)jrow * SEQ + k0 + c * 8);
            pvl[i] = *(const uint4*)(vlg + (size_t)jrow * SEQ + k0 + c * 8);
        }
    };
    auto commit = [&](int buf) {
        __nv_bfloat16* d = fs + buf * FSTAGE;
#pragma unroll
        for (int i = 0; i < 2; ++i) {
            int c = cch + i * 4;
            *(uint4*)(d + jrow * FSTR + c * 8)            = pkh[i];
            *(uint4*)(d + FSUB + jrow * FSTR + c * 8)     = pkl[i];
            *(uint4*)(d + 2 * FSUB + jrow * FSTR + c * 8) = pvh[i];
            *(uint4*)(d + 3 * FSUB + jrow * FSTR + c * 8) = pvl[i];
        }
    };

    const int nkt = 2 * qt + 2;
    prefetch(0);
    commit(0);
    __syncthreads();

    for (int kt = 0; kt < nkt; ++kt) {
        const int k0 = kt * 64;
        const int cur = kt & 1;
        if (kt + 1 < nkt) prefetch((kt + 1) * 64);

        const bool active = (k0 <= q0 + 16 * wid + 15);
        if (active) {
            const uint32_t khB = sbase + (uint32_t)(cur * FSTAGE * 2);
            const uint32_t klB = khB + FSUB * 2;
            const uint32_t vhB = khB + 2 * FSUB * 2;
            const uint32_t vlB = khB + 3 * FSUB * 2;

            float sacc[8][4];
#pragma unroll
            for (int j = 0; j < 8; ++j)
#pragma unroll
                for (int k = 0; k < 4; ++k) sacc[j][k] = 0.0f;

#pragma unroll
            for (int kk = 0; kk < 4; ++kk) {
#pragma unroll
                for (int nt = 0; nt < 4; ++nt) {
                    uint32_t b0, b1, b2, b3, c0, c1, c2, c3;
                    ldmx4(khB + (uint32_t)(((nt * 16 + bRow) * FSTR + kk * 16 + bK) * 2),
                          b0, b1, b2, b3);
                    ldmx4(klB + (uint32_t)(((nt * 16 + bRow) * FSTR + kk * 16 + bK) * 2),
                          c0, c1, c2, c3);
                    mma16816(sacc[2 * nt + 0], qhf[kk], b0, b1);
                    mma16816(sacc[2 * nt + 1], qhf[kk], b2, b3);
                    mma16816(sacc[2 * nt + 0], qlf[kk], b0, b1);
                    mma16816(sacc[2 * nt + 1], qlf[kk], b2, b3);
                    mma16816(sacc[2 * nt + 0], qhf[kk], c0, c1);
                    mma16816(sacc[2 * nt + 1], qhf[kk], c2, c3);
                }
            }

            const int r0 = q0 + 16 * wid + (lane >> 2);
            if (k0 + 63 > q0 + 16 * wid) {
#pragma unroll
                for (int j = 0; j < 8; ++j) {
                    int kc = k0 + j * 8 + (lane & 3) * 2;
                    if (kc     > r0)     sacc[j][0] = -INFINITY;
                    if (kc + 1 > r0)     sacc[j][1] = -INFINITY;
                    if (kc     > r0 + 8) sacc[j][2] = -INFINITY;
                    if (kc + 1 > r0 + 8) sacc[j][3] = -INFINITY;
                }
            }

            float mx0 = -INFINITY, mx1 = -INFINITY;
#pragma unroll
            for (int j = 0; j < 8; ++j) {
                mx0 = fmaxf(mx0, fmaxf(sacc[j][0], sacc[j][1]));
                mx1 = fmaxf(mx1, fmaxf(sacc[j][2], sacc[j][3]));
            }
#pragma unroll
            for (int off = 1; off <= 2; off <<= 1) {
                mx0 = fmaxf(mx0, __shfl_xor_sync(0xffffffffu, mx0, off));
                mx1 = fmaxf(mx1, __shfl_xor_sync(0xffffffffu, mx1, off));
            }
            float mn0 = fmaxf(m0v, mx0), mn1 = fmaxf(m1v, mx1);
            float al0 = __expf(m0v - mn0), al1 = __expf(m1v - mn1);
            m0v = mn0; m1v = mn1;

            uint32_t pah[4][4], pal[4][4];
            float rs0 = 0.0f, rs1 = 0.0f;
#pragma unroll
            for (int t = 0; t < 4; ++t) {
#pragma unroll
                for (int half = 0; half < 2; ++half) {
                    int j = 2 * t + half;
                    float p00 = __expf(sacc[j][0] - mn0);
                    float p01 = __expf(sacc[j][1] - mn0);
                    float p10 = __expf(sacc[j][2] - mn1);
                    float p11 = __expf(sacc[j][3] - mn1);
                    rs0 += p00 + p01;
                    rs1 += p10 + p11;
                    __nv_bfloat16 h00 = __float2bfloat16(p00);
                    __nv_bfloat16 h01 = __float2bfloat16(p01);
                    __nv_bfloat16 h10 = __float2bfloat16(p10);
                    __nv_bfloat16 h11 = __float2bfloat16(p11);
                    pah[t][0 + half * 2] = packbf(h00, h01);
                    pah[t][1 + half * 2] = packbf(h10, h11);
                    pal[t][0 + half * 2] = packbf(
                        __float2bfloat16(p00 - __bfloat162float(h00)),
                        __float2bfloat16(p01 - __bfloat162float(h01)));
                    pal[t][1 + half * 2] = packbf(
                        __float2bfloat16(p10 - __bfloat162float(h10)),
                        __float2bfloat16(p11 - __bfloat162float(h11)));
                }
            }
#pragma unroll
            for (int off = 1; off <= 2; off <<= 1) {
                rs0 += __shfl_xor_sync(0xffffffffu, rs0, off);
                rs1 += __shfl_xor_sync(0xffffffffu, rs1, off);
            }
            l0v = l0v * al0 + rs0;
            l1v = l1v * al1 + rs1;

#pragma unroll
            for (int j = 0; j < 8; ++j) {
                oacc[j][0] *= al0; oacc[j][1] *= al0;
                oacc[j][2] *= al1; oacc[j][3] *= al1;
            }

#pragma unroll
            for (int t = 0; t < 4; ++t) {
#pragma unroll
                for (int nt = 0; nt < 4; ++nt) {
                    uint32_t v0, v1, v2, v3, w0, w1, w2, w3;
                    ldmx4(vhB + (uint32_t)(((nt * 16 + bRow) * FSTR + t * 16 + bK) * 2),
                          v0, v1, v2, v3);
                    ldmx4(vlB + (uint32_t)(((nt * 16 + bRow) * FSTR + t * 16 + bK) * 2),
                          w0, w1, w2, w3);
                    mma16816(oacc[2 * nt + 0], pah[t], v0, v1);
                    mma16816(oacc[2 * nt + 1], pah[t], v2, v3);
                    mma16816(oacc[2 * nt + 0], pal[t], v0, v1);
                    mma16816(oacc[2 * nt + 1], pal[t], v2, v3);
                    mma16816(oacc[2 * nt + 0], pah[t], w0, w1);
                    mma16816(oacc[2 * nt + 1], pah[t], w2, w3);
                }
            }
        }

        if (kt + 1 < nkt) commit((kt + 1) & 1);
        __syncthreads();
    }

    float i0 = 1.0f / l0v, i1 = 1.0f / l1v;
    size_t rowoff = ((size_t)b * SEQ + q0 + 16 * wid + (lane >> 2)) * EMB + h * HDIM;
    __nv_bfloat16* oh = Aoh + rowoff;
    __nv_bfloat16* ol = Aol + rowoff;
#pragma unroll
    for (int j = 0; j < 8; ++j) {
        int col = j * 8 + (lane & 3) * 2;
        float x0 = oacc[j][0] * i0, x1 = oacc[j][1] * i0;
        float y0 = oacc[j][2] * i1, y1 = oacc[j][3] * i1;
        *(uint32_t*)(oh + col)           = hilo_h(x0, x1);
        *(uint32_t*)(ol + col)           = hilo_l(x0, x1);
        *(uint32_t*)(oh + 8 * EMB + col) = hilo_h(y0, y1);
        *(uint32_t*)(ol + 8 * EMB + col) = hilo_l(y0, y1);
    }
}

// ---------------------------------------------------------------------------
// Launch
// ---------------------------------------------------------------------------
extern "C" void kernel_launch(void* const* d_in, const int* in_sizes, int n_in,
                              void* d_out, int out_size)
{
    const float* x  = (const float*)d_in[0];
    const float* Wq = (const float*)d_in[1];
    const float* Wk = (const float*)d_in[2];
    const float* Wv = (const float*)d_in[3];
    const float* Wo = (const float*)d_in[4];
    const float* bo = (const float*)d_in[5];
    float* out = (float*)d_out;

    float* Vp;
    cudaGetSymbolAddress((void**)&Vp, g_V);

    __nv_bfloat16 *xh, *xl, *ah, *al, *wth, *wtl, *woh, *wol;
    __nv_bfloat16 *qh, *ql, *kh, *kl, *vth, *vtl;
    cudaGetSymbolAddress((void**)&xh, g_xh);   cudaGetSymbolAddress((void**)&xl, g_xl);
    cudaGetSymbolAddress((void**)&ah, g_ah);   cudaGetSymbolAddress((void**)&al, g_al);
    cudaGetSymbolAddress((void**)&wth, g_Wth); cudaGetSymbolAddress((void**)&wtl, g_Wtl);
    cudaGetSymbolAddress((void**)&woh, g_Woh); cudaGetSymbolAddress((void**)&wol, g_Wol);
    cudaGetSymbolAddress((void**)&qh, g_qh);   cudaGetSymbolAddress((void**)&ql, g_ql);
    cudaGetSymbolAddress((void**)&kh, g_kh);   cudaGetSymbolAddress((void**)&kl, g_kl);
    cudaGetSymbolAddress((void**)&vth, g_vth); cudaGetSymbolAddress((void**)&vtl, g_vtl);

    cudaFuncSetAttribute(gemm_cp<0>, cudaFuncAttributeMaxDynamicSharedMemorySize, SMEM_GEMM);
    cudaFuncSetAttribute(gemm_cp<1>, cudaFuncAttributeMaxDynamicSharedMemorySize, SMEM_GEMM);
    const int SMEM_FLASH = 2 * FSTAGE * 2;     // 73728 B
    cudaFuncSetAttribute(flash_hmma, cudaFuncAttributeMaxDynamicSharedMemorySize, SMEM_FLASH);

    // 1. Convert x -> bf16 hi/lo
    {
        int n4 = ROWS * EMB / 4;
        convert_hilo<<<(n4 + 255) / 256, 256>>>(x, xh, xl, n4, 1.0f);
    }
    // 2. ALL weight transposes in one launch
    wtrans_all<<<dim3(GK / 32, 160), dim3(32, 8)>>>(Wq, Wk, Wv, Wo, wth, wtl, woh, wol);

    // 3. Fused QKV projection (epilogue writes qh/ql x0.125, kh/kl, fp32 V)
    gemm_cp<1><<<dim3(NQKV / BN, ROWS / BM), 256, SMEM_GEMM>>>(
        xh, xl, wth, wtl, nullptr, 0, nullptr, qh, ql, kh, kl, Vp);

    // 4. Transpose V -> bf16 hi/lo [B,G,D,S]
    vtrans_hilo<<<dim3(SEQ / 32, KVDIM / 32, BATCH), dim3(32, 8)>>>(Vp, vth, vtl);

    // 5. Flash attention (HMMA), writes ah/al directly
    flash_hmma<<<dim3(SEQ / 128, NHEADS, BATCH), 256, SMEM_FLASH>>>(
        qh, ql, kh, kl, vth, vtl, ah, al);

    // 6. Output projection + bias
    gemm_cp<0><<<dim3(EMB / BN, ROWS / BM), 256, SMEM_GEMM>>>(
        ah, al, woh, wol, out, EMB, bo, nullptr, nullptr, nullptr, nullptr, nullptr);
}